// round 1
// baseline (speedup 1.0000x reference)
#include <cuda_runtime.h>
#include <cstdint>

// Problem constants
#define DD   12
#define HH   256
#define WW   256
#define CEc  32
#define HID  256
#define NPATCH 1805      // 5*19*19
#define NPAD   1920      // 15 * 128
#define NP     10000     // 2*8*25*25 patches
#define MPAD   10112     // 79 * 128

#define BM 128
#define BN 128
#define BK 16
#define ASTRIDE 132      // padded to keep LDS.128 16B-aligned, reduce STS conflicts

// Scratch (no allocations allowed — device globals)
__device__ float  g_H[NP * HID];        // relu(emb@W1+b1), 10.24 MB
__device__ float  g_W2p[HID * NPAD];    // W2 padded to 1920 cols, 1.97 MB
__device__ float  g_center[NP];
__device__ float  g_valid[NP];
__device__ double g_acc[3];             // num, sum(m*p*p), sum(m*t)

// ---------------------------------------------------------------- prep
__global__ void k_prep(const float* __restrict__ W2) {
    int idx = blockIdx.x * 256 + threadIdx.x;      // 0 .. 491519 exactly
    if (idx < 3) g_acc[idx] = 0.0;
    int k = idx / NPAD;
    int n = idx - k * NPAD;
    g_W2p[idx] = (n < NPATCH) ? W2[k * NPATCH + n] : 0.f;
}

// ------------------------------------------------- emb gather + MLP1
__global__ void k_mlp1(const float* __restrict__ target,
                       const float* __restrict__ pred,
                       const float* __restrict__ W1,
                       const float* __restrict__ b1) {
    __shared__ float se[CEc];
    int n = blockIdx.x;
    int b  = n / 5000;   int r  = n - b * 5000;
    int pd = r / 625;    int r2 = r - pd * 625;
    int ph = r2 / 25;    int pw = r2 - ph * 25;
    int dc = 2 + pd, hc = 21 + 9 * ph, wc = 21 + 9 * pw;
    int sp = (dc * HH + hc) * WW + wc;              // offset within one (D,H,W)
    int t = threadIdx.x;
    if (t < CEc) se[t] = pred[(b * CEc + t) * (DD * HH * WW) + sp];
    if (t == 32) {
        const float* tg = target + b * 4 * (DD * HH * WW);
        float c0 = tg[sp];
        float a1 = tg[1 * DD * HH * WW + sp];
        float a2 = tg[2 * DD * HH * WW + sp];
        float a3 = tg[3 * DD * HH * WW + sp];
        g_center[n] = c0;
        // valid = (center != 0) && (on_bnd != 1) <=> all three affinities == 1
        g_valid[n] = (c0 != 0.f && a1 == 1.f && a2 == 1.f && a3 == 1.f) ? 1.f : 0.f;
    }
    __syncthreads();
    float acc = b1[t];
#pragma unroll
    for (int c = 0; c < CEc; c++) acc = fmaf(se[c], W1[c * HID + t], acc);
    g_H[n * HID + t] = fmaxf(acc, 0.f);
}

// ---------------------------- MUFU-free sigmoid (exp2 poly + Newton recip)
__device__ __forceinline__ float fast_sigmoid(float z) {
    // e^{-z} = 2^{u}, u = -z*log2(e)
    float u = -z * 1.4426950408889634f;
    u = fminf(fmaxf(u, -125.f), 125.f);
    float tbig = u + 12582912.f;                    // round-to-nearest via magic
    int   ni   = __float_as_int(tbig) - 0x4B400000; // integer part
    float nf   = tbig - 12582912.f;
    float rr   = u - nf;                            // in [-0.5, 0.5]
    float p = 0.0013333558f;                        // 2^r Taylor/minimax deg 5
    p = fmaf(p, rr, 0.0096181291f);
    p = fmaf(p, rr, 0.0555041087f);
    p = fmaf(p, rr, 0.2402265069f);
    p = fmaf(p, rr, 0.6931471806f);
    p = fmaf(p, rr, 1.0f);
    float ez = p * __int_as_float((ni + 127) << 23);
    float d  = 1.f + ez;
    // reciprocal: bit-trick seed (+- 10%) + 3 Newton iterations -> ~1e-8
    float y = __int_as_float(0x7EF311C3 - __float_as_int(d));
    y = y * (2.f - d * y);
    y = y * (2.f - d * y);
    y = y * (2.f - d * y);
    return y;                                       // sigmoid(z)
}

// ---------------------- GEMM (h @ W2) + fused sigmoid/mask/reduction
__global__ __launch_bounds__(256, 2)
void k_gemm(const float* __restrict__ target, const float* __restrict__ b2) {
    __shared__ float As[BK][ASTRIDE];
    __shared__ float Bs[BK][BN];
    __shared__ float red[3][8];

    int tid = threadIdx.x;
    int tx = tid & 15, ty = tid >> 4;
    int n0 = blockIdx.x * BN;
    int m0 = blockIdx.y * BM;

    float acc[8][8];
#pragma unroll
    for (int i = 0; i < 8; i++)
#pragma unroll
        for (int j = 0; j < 8; j++) acc[i][j] = 0.f;

    for (int k0 = 0; k0 < HID; k0 += BK) {
#pragma unroll
        for (int l = 0; l < 2; l++) {
            int idx = l * 256 + tid;
            // A tile 128x16, transposed store As[k][m]
            int row = idx >> 2;
            int q   = (idx & 3) * 4;
            float4 v = make_float4(0.f, 0.f, 0.f, 0.f);
            if (m0 + row < NP)
                v = *(const float4*)&g_H[(m0 + row) * HID + k0 + q];
            As[q + 0][row] = v.x; As[q + 1][row] = v.y;
            As[q + 2][row] = v.z; As[q + 3][row] = v.w;
            // B tile 16x128
            int brow = idx >> 5;
            int bcol = (idx & 31) * 4;
            *(float4*)&Bs[brow][bcol] =
                *(const float4*)&g_W2p[(k0 + brow) * NPAD + n0 + bcol];
        }
        __syncthreads();
#pragma unroll
        for (int kk = 0; kk < BK; kk++) {
            float a[8], bb[8];
            *(float4*)&a[0]  = *(const float4*)&As[kk][ty * 4];
            *(float4*)&a[4]  = *(const float4*)&As[kk][64 + ty * 4];
            *(float4*)&bb[0] = *(const float4*)&Bs[kk][tx * 4];
            *(float4*)&bb[4] = *(const float4*)&Bs[kk][64 + tx * 4];
#pragma unroll
            for (int i = 0; i < 8; i++)
#pragma unroll
                for (int j = 0; j < 8; j++)
                    acc[i][j] = fmaf(a[i], bb[j], acc[i][j]);
        }
        __syncthreads();
    }

    // Fused epilogue: sigmoid + target/ignore masks from gt + partial sums
    float s_num = 0.f, s_dp = 0.f, s_dt = 0.f;
#pragma unroll
    for (int i = 0; i < 8; i++) {
        int mloc = (i < 4) ? (ty * 4 + i) : (64 + ty * 4 + i - 4);
        int m = m0 + mloc;
        if (m < NP) {
            float cen = g_center[m];
            float vfl = g_valid[m];
            int b  = m / 5000;  int r  = m - b * 5000;
            int pd = r / 625;   int r2 = r - pd * 625;
            int ph = r2 / 25;   int pw = r2 - ph * 25;
            const float* gtb = target + b * 4 * (DD * HH * WW) + pd * (HH * WW);
            int hb = 2 + 9 * ph, wb = 2 + 9 * pw;
#pragma unroll
            for (int j = 0; j < 8; j++) {
                int nloc = (j < 4) ? (tx * 4 + j) : (64 + tx * 4 + j - 4);
                int n = n0 + nloc;
                if (n < NPATCH) {
                    int dp = n / 361;
                    int rr = n - dp * 361;
                    int ii = rr / 19;
                    int jw = rr - ii * 19;
                    const float* g = gtb + dp * (HH * WW)
                                   + (hb + 2 * ii) * WW + (wb + 2 * jw);
                    float g0 = g[0], g1 = g[1], g2 = g[WW], g3 = g[WW + 1];
                    float tgt = (g0 != cen || g1 != cen || g2 != cen || g3 != cen)
                                ? 1.f : 0.f;
                    bool  ig  = (g0 == 0.f || g1 == 0.f || g2 == 0.f || g3 == 0.f);
                    float msk = ig ? 0.f : vfl;
                    float zz  = acc[i][j] + b2[n];
                    float pp  = fast_sigmoid(zz);
                    float pm  = pp * msk;
                    s_num = fmaf(pm, tgt, s_num);   // m*p*t
                    s_dp  = fmaf(pm, pp,  s_dp);    // m*p*p
                    s_dt  = fmaf(msk, tgt, s_dt);   // m*t  (t==t*t)
                }
            }
        }
    }

    // block reduction -> 3 double atomics
#pragma unroll
    for (int off = 16; off; off >>= 1) {
        s_num += __shfl_xor_sync(0xffffffffu, s_num, off);
        s_dp  += __shfl_xor_sync(0xffffffffu, s_dp,  off);
        s_dt  += __shfl_xor_sync(0xffffffffu, s_dt,  off);
    }
    int wid = tid >> 5, lane = tid & 31;
    if (lane == 0) { red[0][wid] = s_num; red[1][wid] = s_dp; red[2][wid] = s_dt; }
    __syncthreads();
    if (tid == 0) {
        float a0 = 0.f, a1 = 0.f, a2 = 0.f;
#pragma unroll
        for (int w = 0; w < 8; w++) { a0 += red[0][w]; a1 += red[1][w]; a2 += red[2][w]; }
        atomicAdd(&g_acc[0], (double)a0);
        atomicAdd(&g_acc[1], (double)a1);
        atomicAdd(&g_acc[2], (double)a2);
    }
}

// ---------------------------------------------------------------- final
__global__ void k_final(float* out) {
    double num = g_acc[0];
    double den = g_acc[1] + g_acc[2];
    if (den < 1e-6) den = 1e-6;
    out[0] = (float)(-2.0 * num / den);
}

// ---------------------------------------------------------------- launch
extern "C" void kernel_launch(void* const* d_in, const int* in_sizes, int n_in,
                              void* d_out, int out_size) {
    const float* target = (const float*)d_in[0];
    const float* pred   = (const float*)d_in[1];
    const float* W1     = (const float*)d_in[2];
    const float* b1     = (const float*)d_in[3];
    const float* W2     = (const float*)d_in[4];
    const float* b2     = (const float*)d_in[5];

    k_prep<<<(HID * NPAD) / 256, 256>>>(W2);
    k_mlp1<<<NP, 256>>>(target, pred, W1, b1);
    k_gemm<<<dim3(NPAD / BN, MPAD / BM), 256>>>(target, b2);
    k_final<<<1, 1>>>((float*)d_out);
}

// round 6
// speedup vs baseline: 2.5968x; 2.5968x over previous
#include <cuda_runtime.h>
#include <cuda_bf16.h>
#include <cstdint>

// ---------------- problem constants ----------------
#define DD   12
#define HH   256
#define WW   256
#define HW_  (HH*WW)
#define DHW  (DD*HH*WW)
#define CEc  32
#define HID  256
#define NPATCH 1805      // 5*19*19
#define NPAD   1920      // 15 * 128
#define NP     10000     // 2*8*25*25 patches
#define MT     79        // ceil(10000/128)
#define NT     15        // 1920/128

// ---------------- scratch (device globals, no allocs allowed) -----------
__device__ __nv_bfloat16 g_Hb[NP * HID];        // relu(emb@W1+b1), bf16
__device__ __nv_bfloat16 g_W2Tb[NPAD * HID];    // W2^T padded, bf16 [n][k]
__device__ float  g_center[NP];
__device__ float  g_valid[NP];
__device__ int    g_noff[NPAD];                 // per-n gt window offset, -1 pad
__device__ float2 g_wmm[2 * DHW];               // (min,max) of 2x2 gt window
__device__ double g_acc[3];                     // num, sum(m*p*p), sum(m*t)

// ======================= helpers ==========================
__device__ __forceinline__ uint32_t smem_u32(const void* p) {
    uint32_t a;
    asm("{ .reg .u64 t; cvta.to.shared.u64 t, %1; cvt.u32.u64 %0, t; }"
        : "=r"(a) : "l"(p));
    return a;
}
__device__ __forceinline__ float sigmoid_mufu(float z) {
    float u = -1.4426950408889634f * z;
    float ez; asm("ex2.approx.f32 %0, %1;" : "=f"(ez) : "f"(u));
    float d = 1.0f + ez;
    float r; asm("rcp.approx.f32 %0, %1;" : "=f"(r) : "f"(d));
    return r;
}

// ============================ prep ======================================
__global__ void k_prep(const float* __restrict__ W2) {
    int idx = blockIdx.x * 256 + threadIdx.x;          // 0 .. 491519
    if (idx < 3) g_acc[idx] = 0.0;
    if (idx < NPAD) {
        int n = idx;
        if (n < NPATCH) {
            int dp = n / 361, rr = n - dp * 361;
            int ii = rr / 19, jw = rr - ii * 19;
            g_noff[n] = dp * HW_ + 2 * ii * WW + 2 * jw;
        } else g_noff[n] = -1;
    }
    int k = idx / NPAD;
    int n = idx - k * NPAD;
    float v = (n < NPATCH) ? W2[k * NPATCH + n] : 0.f;
    g_W2Tb[n * HID + k] = __float2bfloat16(v);
}

// ============ window min/max field over gt (2x2, stride-1 grid) =========
__global__ void k_window(const float* __restrict__ target) {
    int idx = blockIdx.x * 256 + threadIdx.x;          // 2*DHW = 1,572,864
    int b = idx / DHW; int r = idx - b * DHW;
    int d = r / HW_;   int hw = r - d * HW_;
    int h = hw >> 8;   int w = hw & 255;
    const float* g = target + (long)b * 4 * DHW + d * HW_ + hw;
    float g0 = g[0];
    float g1 = (w < 255) ? g[1] : g0;
    float g2 = (h < 255) ? g[WW] : g0;
    float g3 = (h < 255 && w < 255) ? g[WW + 1] : g0;
    float mn = fminf(fminf(g0, g1), fminf(g2, g3));
    float mx = fmaxf(fmaxf(g0, g1), fmaxf(g2, g3));
    g_wmm[idx] = make_float2(mn, mx);
}

// ====================== emb gather + MLP1 (bf16 out) ====================
#define PPB 50
__global__ __launch_bounds__(256)
void k_mlp1(const float* __restrict__ target, const float* __restrict__ pred,
            const float* __restrict__ W1, const float* __restrict__ b1) {
    __shared__ float W1s[CEc * HID];
    __shared__ float embs[PPB * CEc];
    int tid = threadIdx.x;
    int pbase = blockIdx.x * PPB;

    for (int i = tid; i < CEc * HID; i += 256) W1s[i] = W1[i];

    for (int i = tid; i < PPB * CEc; i += 256) {
        int c = i / PPB, p = i - c * PPB;
        int n = pbase + p;
        int b = n / 5000;  int r = n - b * 5000;
        int pd = r / 625;  int r2 = r - pd * 625;
        int ph = r2 / 25;  int pw = r2 - ph * 25;
        int sp = ((2 + pd) * HH + (21 + 9 * ph)) * WW + (21 + 9 * pw);
        embs[p * CEc + c] = pred[(b * CEc + c) * DHW + sp];
    }
    if (tid < PPB) {
        int n = pbase + tid;
        int b = n / 5000;  int r = n - b * 5000;
        int pd = r / 625;  int r2 = r - pd * 625;
        int ph = r2 / 25;  int pw = r2 - ph * 25;
        int sp = ((2 + pd) * HH + (21 + 9 * ph)) * WW + (21 + 9 * pw);
        const float* tg = target + b * 4 * DHW;
        float c0 = tg[sp];
        float a1 = tg[1 * DHW + sp];
        float a2 = tg[2 * DHW + sp];
        float a3 = tg[3 * DHW + sp];
        g_center[n] = c0;
        g_valid[n] = (c0 != 0.f && a1 == 1.f && a2 == 1.f && a3 == 1.f) ? 1.f : 0.f;
    }
    __syncthreads();

    float bb = b1[tid];
    for (int p = 0; p < PPB; p++) {
        float acc = bb;
        const float* e = &embs[p * CEc];
#pragma unroll
        for (int c = 0; c < CEc; c++) acc = fmaf(e[c], W1s[c * HID + tid], acc);
        g_Hb[(pbase + p) * HID + tid] = __float2bfloat16(fmaxf(acc, 0.f));
    }
}

// ============ mma.sync bf16 GEMM (h @ W2) + fused epilogue ==============
// SMEM per buffer: A 128x32 bf16 (8KB), B 128x32 bf16 (8KB).
// Layout: row stride 64B (4 x 16B chunks); chunk swizzle c ^= (row>>1)&3.
__global__ __launch_bounds__(256, 2)
void k_gemm(const float2* __restrict__ gw, const float* __restrict__ b2) {
    __shared__ __align__(128) char As[2][8192];
    __shared__ __align__(128) char Bs[2][8192];
    __shared__ float b2s[128];
    __shared__ int   noffs[128];
    __shared__ float red[3][8];

    int tid = threadIdx.x;
    int wid = tid >> 5, lane = tid & 31;
    int n0 = blockIdx.x * 128;
    int m0 = blockIdx.y * 128;

    if (tid < 128) {
        int n = n0 + tid;
        b2s[tid]  = (n < NPATCH) ? b2[n] : 0.f;
        noffs[tid] = g_noff[n];
    }

    float c[4][4][4];
#pragma unroll
    for (int mi = 0; mi < 4; mi++)
#pragma unroll
        for (int ni = 0; ni < 4; ni++)
#pragma unroll
            for (int k = 0; k < 4; k++) c[mi][ni][k] = 0.f;

    int wm = (wid >> 2) * 64;     // warp m-base within tile
    int wn = (wid & 3) * 32;      // warp n-base within tile
    int jj = lane >> 3, rr = lane & 7;

    // ---- stage loader: 128 rows x 32 k (4 x 16B chunks per row) ----
    auto stage = [&](int it, int buf) {
        int k0 = it * 32;
#pragma unroll
        for (int l = 0; l < 2; l++) {
            int i = l * 256 + tid;
            int r = i >> 2;
            int cch = i & 3;
            uint32_t sw = (uint32_t)(r * 64 + ((cch ^ ((r >> 1) & 3)) * 16));
            {
                bool ok = (m0 + r < NP);
                const void* src = ok ? (const void*)&g_Hb[(m0 + r) * HID + k0 + cch * 8]
                                     : (const void*)&g_Hb[0];
                uint32_t dst = smem_u32(&As[buf][sw]);
                int sz = ok ? 16 : 0;
                asm volatile("cp.async.cg.shared.global [%0], [%1], 16, %2;\n"
                             :: "r"(dst), "l"(src), "r"(sz));
            }
            {
                const void* src = &g_W2Tb[(n0 + r) * HID + k0 + cch * 8];
                uint32_t dst = smem_u32(&Bs[buf][sw]);
                asm volatile("cp.async.cg.shared.global [%0], [%1], 16;\n"
                             :: "r"(dst), "l"(src));
            }
        }
        asm volatile("cp.async.commit_group;\n" ::: "memory");
    };

    stage(0, 0);
    for (int it = 0; it < 8; it++) {
        int buf = it & 1;
        if (it < 7) {
            stage(it + 1, buf ^ 1);
            asm volatile("cp.async.wait_group 1;\n" ::: "memory");
        } else {
            asm volatile("cp.async.wait_group 0;\n" ::: "memory");
        }
        __syncthreads();

#pragma unroll
        for (int s = 0; s < 2; s++) {          // two k16 steps per BK=32
            uint32_t a[4][4], b[2][4];
#pragma unroll
            for (int mi = 0; mi < 4; mi++) {
                int mrow = wm + mi * 16 + (jj & 1) * 8 + rr;
                int ch = s * 2 + (jj >> 1);
                uint32_t addr = smem_u32(
                    &As[buf][mrow * 64 + ((ch ^ ((mrow >> 1) & 3)) * 16)]);
                asm volatile(
                    "ldmatrix.sync.aligned.m8n8.x4.shared.b16 {%0,%1,%2,%3}, [%4];"
                    : "=r"(a[mi][0]), "=r"(a[mi][1]), "=r"(a[mi][2]), "=r"(a[mi][3])
                    : "r"(addr));
            }
#pragma unroll
            for (int nb = 0; nb < 2; nb++) {
                int nrow = wn + nb * 16 + (jj >> 1) * 8 + rr;
                int ch = s * 2 + (jj & 1);
                uint32_t addr = smem_u32(
                    &Bs[buf][nrow * 64 + ((ch ^ ((nrow >> 1) & 3)) * 16)]);
                asm volatile(
                    "ldmatrix.sync.aligned.m8n8.x4.shared.b16 {%0,%1,%2,%3}, [%4];"
                    : "=r"(b[nb][0]), "=r"(b[nb][1]), "=r"(b[nb][2]), "=r"(b[nb][3])
                    : "r"(addr));
            }
#pragma unroll
            for (int mi = 0; mi < 4; mi++)
#pragma unroll
                for (int ni = 0; ni < 4; ni++) {
                    uint32_t bb0 = b[ni >> 1][(ni & 1) * 2 + 0];
                    uint32_t bb1 = b[ni >> 1][(ni & 1) * 2 + 1];
                    asm volatile(
                        "mma.sync.aligned.m16n8k16.row.col.f32.bf16.bf16.f32 "
                        "{%0,%1,%2,%3},{%4,%5,%6,%7},{%8,%9},{%0,%1,%2,%3};"
                        : "+f"(c[mi][ni][0]), "+f"(c[mi][ni][1]),
                          "+f"(c[mi][ni][2]), "+f"(c[mi][ni][3])
                        : "r"(a[mi][0]), "r"(a[mi][1]), "r"(a[mi][2]), "r"(a[mi][3]),
                          "r"(bb0), "r"(bb1));
                }
        }
        __syncthreads();
    }

    // ---- fused epilogue: sigmoid + masks (from precomputed window field) ----
    float s_num = 0.f, s_dp = 0.f, s_dt = 0.f;
#pragma unroll
    for (int mi = 0; mi < 4; mi++)
#pragma unroll
        for (int h = 0; h < 2; h++) {
            int mloc = wm + mi * 16 + (lane >> 2) + h * 8;
            int m = m0 + mloc;
            if (m >= NP) continue;
            float vfl = g_valid[m];
            if (vfl == 0.f) continue;
            float cen = g_center[m];
            int b_ = m / 5000;  int r_ = m - b_ * 5000;
            int pd = r_ / 625;  int r2 = r_ - pd * 625;
            int ph = r2 / 25;   int pw = r2 - ph * 25;
            long gb = (long)(b_ * DD + pd) * HW_
                    + (2 + 9 * ph) * WW + (2 + 9 * pw);
#pragma unroll
            for (int ni = 0; ni < 4; ni++)
#pragma unroll
                for (int q = 0; q < 2; q++) {
                    int nloc = wn + ni * 8 + (lane & 3) * 2 + q;
                    int off = noffs[nloc];
                    if (off < 0) continue;
                    float2 wmm = gw[gb + off];
                    float tgt = (wmm.x != cen || wmm.y != cen) ? 1.f : 0.f;
                    float msk = (wmm.x == 0.f) ? 0.f : vfl;
                    float z = c[mi][ni][h * 2 + q] + b2s[nloc];
                    float p = sigmoid_mufu(z);
                    float pm = p * msk;
                    s_num = fmaf(pm, tgt, s_num);
                    s_dp  = fmaf(pm, p,  s_dp);
                    s_dt  = fmaf(msk, tgt, s_dt);
                }
        }

    // ---- reduce + atomics ----
#pragma unroll
    for (int o = 16; o; o >>= 1) {
        s_num += __shfl_xor_sync(0xffffffffu, s_num, o);
        s_dp  += __shfl_xor_sync(0xffffffffu, s_dp,  o);
        s_dt  += __shfl_xor_sync(0xffffffffu, s_dt,  o);
    }
    if (lane == 0) { red[0][wid] = s_num; red[1][wid] = s_dp; red[2][wid] = s_dt; }
    __syncthreads();
    if (tid == 0) {
        float a0 = 0, a1 = 0, a2 = 0;
#pragma unroll
        for (int w = 0; w < 8; w++) { a0 += red[0][w]; a1 += red[1][w]; a2 += red[2][w]; }
        atomicAdd(&g_acc[0], (double)a0);
        atomicAdd(&g_acc[1], (double)a1);
        atomicAdd(&g_acc[2], (double)a2);
    }
}

// ============================ final =====================================
__global__ void k_final(float* out) {
    double num = g_acc[0];
    double den = g_acc[1] + g_acc[2];
    if (den < 1e-6) den = 1e-6;
    out[0] = (float)(-2.0 * num / den);
}

// ============================ launch ====================================
extern "C" void kernel_launch(void* const* d_in, const int* in_sizes, int n_in,
                              void* d_out, int out_size) {
    const float* target = (const float*)d_in[0];
    const float* pred   = (const float*)d_in[1];
    const float* W1     = (const float*)d_in[2];
    const float* b1     = (const float*)d_in[3];
    const float* W2     = (const float*)d_in[4];
    const float* b2     = (const float*)d_in[5];

    float2* gw;
    cudaGetSymbolAddress((void**)&gw, g_wmm);

    k_prep<<<(HID * NPAD) / 256, 256>>>(W2);
    k_window<<<(2 * DHW) / 256, 256>>>(target);
    k_mlp1<<<NP / PPB, 256>>>(target, pred, W1, b1);
    k_gemm<<<dim3(NT, MT), 256>>>(gw, b2);
    k_final<<<1, 1>>>((float*)d_out);
}

// round 8
// speedup vs baseline: 2.8214x; 1.0865x over previous
#include <cuda_runtime.h>
#include <cuda_bf16.h>
#include <cstdint>

// ---------------- problem constants ----------------
#define DD   12
#define HH   256
#define WW   256
#define HW_  (HH*WW)
#define DHW  (DD*HH*WW)
#define CEc  32
#define HID  256
#define NPATCH 1805      // 5*19*19
#define NPAD   1920      // 15 * 128
#define NP     10000     // 2*8*25*25 patches
#define MT     79        // ceil(10000/128)
#define NT     15        // 1920/128

// ---------------- scratch (device globals, no allocs allowed) -----------
__device__ __nv_bfloat16 g_Hb[NP * HID];        // relu(emb@W1+b1), bf16
__device__ __nv_bfloat16 g_W2Tb[NPAD * HID];    // W2^T padded, bf16 [n][k]
__device__ float    g_center[NP];
__device__ float    g_valid[NP];
__device__ int      g_noff[NPAD];               // per-n gt window offset, -1 pad
__device__ uint32_t g_wpk[2 * DHW];             // packed (min|max<<16) 2x2 window
__device__ double   g_acc[3];                   // num, sum(m*p*p), sum(m*t)

// ======================= helpers ==========================
__device__ __forceinline__ uint32_t smem_u32(const void* p) {
    uint32_t a;
    asm("{ .reg .u64 t; cvta.to.shared.u64 t, %1; cvt.u32.u64 %0, t; }"
        : "=r"(a) : "l"(p));
    return a;
}
__device__ __forceinline__ float sigmoid_mufu(float z) {
    float u = -1.4426950408889634f * z;
    float ez; asm("ex2.approx.f32 %0, %1;" : "=f"(ez) : "f"(u));
    float d = 1.0f + ez;
    float r; asm("rcp.approx.f32 %0, %1;" : "=f"(r) : "f"(d));
    return r;
}

// ============================ prep ======================================
__global__ void k_prep(const float* __restrict__ W2) {
    int idx = blockIdx.x * 256 + threadIdx.x;          // 0 .. 491519
    if (idx < 3) g_acc[idx] = 0.0;
    if (idx < NPAD) {
        int n = idx;
        if (n < NPATCH) {
            int dp = n / 361, rr = n - dp * 361;
            int ii = rr / 19, jw = rr - ii * 19;
            g_noff[n] = dp * HW_ + 2 * ii * WW + 2 * jw;
        } else g_noff[n] = -1;
    }
    int k = idx / NPAD;
    int n = idx - k * NPAD;
    float v = (n < NPATCH) ? W2[k * NPATCH + n] : 0.f;
    g_W2Tb[n * HID + k] = __float2bfloat16(v);
}

// ======== packed window min/max field over gt (2x2, stride-1 grid) ======
__global__ void k_window(const float* __restrict__ target) {
    int idx = blockIdx.x * 256 + threadIdx.x;          // 2*DHW
    int b = idx / DHW; int r = idx - b * DHW;
    int d = r / HW_;   int hw = r - d * HW_;
    int h = hw >> 8;   int w = hw & 255;
    const float* g = target + (long)b * 4 * DHW + d * HW_ + hw;
    float g0 = g[0];
    float g1 = (w < 255) ? g[1] : g0;
    float g2 = (h < 255) ? g[WW] : g0;
    float g3 = (h < 255 && w < 255) ? g[WW + 1] : g0;
    int mn = (int)fminf(fminf(g0, g1), fminf(g2, g3));
    int mx = (int)fmaxf(fmaxf(g0, g1), fmaxf(g2, g3));
    g_wpk[idx] = (uint32_t)mn | ((uint32_t)mx << 16);
}

// ====================== emb gather + MLP1 (bf16 out) ====================
#define PPB 50
__global__ __launch_bounds__(256)
void k_mlp1(const float* __restrict__ target, const float* __restrict__ pred,
            const float* __restrict__ W1, const float* __restrict__ b1) {
    __shared__ float W1s[CEc * HID];
    __shared__ float embs[PPB * CEc];
    int tid = threadIdx.x;
    int pbase = blockIdx.x * PPB;

    for (int i = tid; i < CEc * HID; i += 256) W1s[i] = W1[i];

    for (int i = tid; i < PPB * CEc; i += 256) {
        int c = i / PPB, p = i - c * PPB;
        int n = pbase + p;
        int b = n / 5000;  int r = n - b * 5000;
        int pd = r / 625;  int r2 = r - pd * 625;
        int ph = r2 / 25;  int pw = r2 - ph * 25;
        int sp = ((2 + pd) * HH + (21 + 9 * ph)) * WW + (21 + 9 * pw);
        embs[p * CEc + c] = pred[(b * CEc + c) * DHW + sp];
    }
    if (tid < PPB) {
        int n = pbase + tid;
        int b = n / 5000;  int r = n - b * 5000;
        int pd = r / 625;  int r2 = r - pd * 625;
        int ph = r2 / 25;  int pw = r2 - ph * 25;
        int sp = ((2 + pd) * HH + (21 + 9 * ph)) * WW + (21 + 9 * pw);
        const float* tg = target + b * 4 * DHW;
        float c0 = tg[sp];
        float a1 = tg[1 * DHW + sp];
        float a2 = tg[2 * DHW + sp];
        float a3 = tg[3 * DHW + sp];
        g_center[n] = c0;
        g_valid[n] = (c0 != 0.f && a1 == 1.f && a2 == 1.f && a3 == 1.f) ? 1.f : 0.f;
    }
    __syncthreads();

    float bb = b1[tid];
    for (int p = 0; p < PPB; p++) {
        float acc = bb;
        const float* e = &embs[p * CEc];
#pragma unroll
        for (int c = 0; c < CEc; c++) acc = fmaf(e[c], W1s[c * HID + tid], acc);
        g_Hb[(pbase + p) * HID + tid] = __float2bfloat16(fmaxf(acc, 0.f));
    }
}

// ============ mma.sync bf16 GEMM (h @ W2) + fused epilogue ==============
// 3-stage cp.async pipeline, BK=32. A/B tiles 128x32 bf16 = 8KB each.
// Row stride 64B (4 x 16B chunks); chunk swizzle c ^= (row>>1)&3.
#define STG 3
__global__ __launch_bounds__(256, 2)
void k_gemm(const uint32_t* __restrict__ gwp, const float* __restrict__ b2) {
    __shared__ __align__(128) char As[STG][8192];
    __shared__ __align__(128) char Bs[STG][8192];

    int tid = threadIdx.x;
    int wid = tid >> 5, lane = tid & 31;
    int n0 = blockIdx.x * 128;
    int m0 = blockIdx.y * 128;

    float c[4][4][4];
#pragma unroll
    for (int mi = 0; mi < 4; mi++)
#pragma unroll
        for (int ni = 0; ni < 4; ni++)
#pragma unroll
            for (int k = 0; k < 4; k++) c[mi][ni][k] = 0.f;

    int wm = (wid >> 2) * 64;     // warp m-base within tile
    int wn = (wid & 3) * 32;      // warp n-base within tile
    int jj = lane >> 3, rr = lane & 7;

    // ---- precompute ldmatrix smem addresses (buffer 0) ----
    uint32_t aA[2][4], bA[2][2];
    uint32_t abase = smem_u32(&As[0][0]);
    uint32_t bbase = smem_u32(&Bs[0][0]);
#pragma unroll
    for (int s = 0; s < 2; s++) {
#pragma unroll
        for (int mi = 0; mi < 4; mi++) {
            int mrow = wm + mi * 16 + (jj & 1) * 8 + rr;
            int ch = s * 2 + (jj >> 1);
            aA[s][mi] = abase + mrow * 64 + ((ch ^ ((mrow >> 1) & 3)) * 16);
        }
#pragma unroll
        for (int nb = 0; nb < 2; nb++) {
            int nrow = wn + nb * 16 + (jj >> 1) * 8 + rr;
            int ch = s * 2 + (jj & 1);
            bA[s][nb] = bbase + nrow * 64 + ((ch ^ ((nrow >> 1) & 3)) * 16);
        }
    }

    // ---- precompute per-thread staging addresses (2 chunks per matrix) ----
    uint32_t stDst[2];
    const char* stA[2];
    const char* stB[2];
    int stSz[2];
#pragma unroll
    for (int l = 0; l < 2; l++) {
        int i = l * 256 + tid;
        int r = i >> 2;
        int cch = i & 3;
        stDst[l] = (uint32_t)(r * 64 + ((cch ^ ((r >> 1) & 3)) * 16));
        bool ok = (m0 + r < NP);
        stA[l] = ok ? (const char*)&g_Hb[(m0 + r) * HID + cch * 8]
                    : (const char*)&g_Hb[0];
        stSz[l] = ok ? 16 : 0;
        stB[l] = (const char*)&g_W2Tb[(n0 + r) * HID + cch * 8];
    }

    auto stage = [&](int it, int buf) {
        int koff = it * 64;                    // 32 bf16 = 64 bytes
#pragma unroll
        for (int l = 0; l < 2; l++) {
            uint32_t da = abase + buf * 8192 + stDst[l];
            uint32_t db = bbase + buf * 8192 + stDst[l];
            asm volatile("cp.async.cg.shared.global [%0], [%1], 16, %2;\n"
                         :: "r"(da), "l"(stA[l] + koff), "r"(stSz[l]));
            asm volatile("cp.async.cg.shared.global [%0], [%1], 16;\n"
                         :: "r"(db), "l"(stB[l] + koff));
        }
        asm volatile("cp.async.commit_group;\n" ::: "memory");
    };

    stage(0, 0);
    stage(1, 1);
    for (int it = 0; it < 8; it++) {
        if (it < 7)
            asm volatile("cp.async.wait_group 1;\n" ::: "memory");
        else
            asm volatile("cp.async.wait_group 0;\n" ::: "memory");
        __syncthreads();
        if (it + 2 < 8) stage(it + 2, (it + 2) % STG);

        uint32_t boff = (uint32_t)((it % STG) * 8192);
#pragma unroll
        for (int s = 0; s < 2; s++) {
            uint32_t a[4][4], b[2][4];
#pragma unroll
            for (int mi = 0; mi < 4; mi++)
                asm volatile(
                    "ldmatrix.sync.aligned.m8n8.x4.shared.b16 {%0,%1,%2,%3}, [%4];"
                    : "=r"(a[mi][0]), "=r"(a[mi][1]), "=r"(a[mi][2]), "=r"(a[mi][3])
                    : "r"(aA[s][mi] + boff));
#pragma unroll
            for (int nb = 0; nb < 2; nb++)
                asm volatile(
                    "ldmatrix.sync.aligned.m8n8.x4.shared.b16 {%0,%1,%2,%3}, [%4];"
                    : "=r"(b[nb][0]), "=r"(b[nb][1]), "=r"(b[nb][2]), "=r"(b[nb][3])
                    : "r"(bA[s][nb] + boff));
#pragma unroll
            for (int mi = 0; mi < 4; mi++)
#pragma unroll
                for (int ni = 0; ni < 4; ni++) {
                    uint32_t bb0 = b[ni >> 1][(ni & 1) * 2 + 0];
                    uint32_t bb1 = b[ni >> 1][(ni & 1) * 2 + 1];
                    asm volatile(
                        "mma.sync.aligned.m16n8k16.row.col.f32.bf16.bf16.f32 "
                        "{%0,%1,%2,%3},{%4,%5,%6,%7},{%8,%9},{%0,%1,%2,%3};"
                        : "+f"(c[mi][ni][0]), "+f"(c[mi][ni][1]),
                          "+f"(c[mi][ni][2]), "+f"(c[mi][ni][3])
                        : "r"(a[mi][0]), "r"(a[mi][1]), "r"(a[mi][2]), "r"(a[mi][3]),
                          "r"(bb0), "r"(bb1));
                }
        }
        __syncthreads();
    }

    // ---- per-thread n-metadata (registers, not smem) ----
    int   off8[8];
    float b28[8];
#pragma unroll
    for (int ni = 0; ni < 4; ni++)
#pragma unroll
        for (int q = 0; q < 2; q++) {
            int n = n0 + wn + ni * 8 + (lane & 3) * 2 + q;
            int o = __ldg(&g_noff[n]);
            off8[ni * 2 + q] = o;
            b28[ni * 2 + q] = (o >= 0) ? __ldg(&b2[n]) : 0.f;
        }

    // ---- fused epilogue: sigmoid + masks from packed window field ----
    float s_num = 0.f, s_dp = 0.f, s_dt = 0.f;
#pragma unroll
    for (int mi = 0; mi < 4; mi++)
#pragma unroll
        for (int h = 0; h < 2; h++) {
            int mloc = wm + mi * 16 + (lane >> 2) + h * 8;
            int m = m0 + mloc;
            if (m >= NP) continue;
            float vfl = g_valid[m];
            if (vfl == 0.f) continue;
            uint32_t cenpk = (uint32_t)(int)g_center[m] * 0x10001u;
            int b_ = m / 5000;  int r_ = m - b_ * 5000;
            int pd = r_ / 625;  int r2 = r_ - pd * 625;
            int ph = r2 / 25;   int pw = r2 - ph * 25;
            long gb = (long)(b_ * DD + pd) * HW_
                    + (2 + 9 * ph) * WW + (2 + 9 * pw);
#pragma unroll
            for (int ni = 0; ni < 4; ni++)
#pragma unroll
                for (int q = 0; q < 2; q++) {
                    int off = off8[ni * 2 + q];
                    if (off < 0) continue;
                    uint32_t w = __ldg(&gwp[gb + off]);
                    float tgt = (w != cenpk) ? 1.f : 0.f;
                    float msk = ((w & 0xFFFFu) == 0u) ? 0.f : vfl;
                    float z = c[mi][ni][h * 2 + q] + b28[ni * 2 + q];
                    float p = sigmoid_mufu(z);
                    float pm = p * msk;
                    s_num = fmaf(pm, tgt, s_num);
                    s_dp  = fmaf(pm, p,  s_dp);
                    s_dt  = fmaf(msk, tgt, s_dt);
                }
        }

    // ---- reduce (scratch reuses A tile) + atomics ----
#pragma unroll
    for (int o = 16; o; o >>= 1) {
        s_num += __shfl_xor_sync(0xffffffffu, s_num, o);
        s_dp  += __shfl_xor_sync(0xffffffffu, s_dp,  o);
        s_dt  += __shfl_xor_sync(0xffffffffu, s_dt,  o);
    }
    float* red = (float*)&As[0][0];
    __syncthreads();
    if (lane == 0) {
        red[wid * 3 + 0] = s_num;
        red[wid * 3 + 1] = s_dp;
        red[wid * 3 + 2] = s_dt;
    }
    __syncthreads();
    if (tid == 0) {
        float a0 = 0, a1 = 0, a2 = 0;
#pragma unroll
        for (int w = 0; w < 8; w++) {
            a0 += red[w * 3 + 0]; a1 += red[w * 3 + 1]; a2 += red[w * 3 + 2];
        }
        atomicAdd(&g_acc[0], (double)a0);
        atomicAdd(&g_acc[1], (double)a1);
        atomicAdd(&g_acc[2], (double)a2);
    }
}

// ============================ final =====================================
__global__ void k_final(float* out) {
    double num = g_acc[0];
    double den = g_acc[1] + g_acc[2];
    if (den < 1e-6) den = 1e-6;
    out[0] = (float)(-2.0 * num / den);
}

// ============================ launch ====================================
extern "C" void kernel_launch(void* const* d_in, const int* in_sizes, int n_in,
                              void* d_out, int out_size) {
    const float* target = (const float*)d_in[0];
    const float* pred   = (const float*)d_in[1];
    const float* W1     = (const float*)d_in[2];
    const float* b1     = (const float*)d_in[3];
    const float* W2     = (const float*)d_in[4];
    const float* b2     = (const float*)d_in[5];

    uint32_t* gwp;
    cudaGetSymbolAddress((void**)&gwp, g_wpk);

    k_prep<<<(HID * NPAD) / 256, 256>>>(W2);
    k_window<<<(2 * DHW) / 256, 256>>>(target);
    k_mlp1<<<NP / PPB, 256>>>(target, pred, W1, b1);
    k_gemm<<<dim3(NT, MT), 256>>>(gwp, b2);
    k_final<<<1, 1>>>((float*)d_out);
}

// round 10
// speedup vs baseline: 2.8298x; 1.0030x over previous
#include <cuda_runtime.h>
#include <cuda_bf16.h>
#include <cstdint>

// ---------------- problem constants ----------------
#define DD   12
#define HH   256
#define WW   256
#define HW_  (HH*WW)
#define DHW  (DD*HH*WW)
#define CEc  32
#define HID  256
#define NPATCH 1805      // 5*19*19
#define NPAD   1920      // 15 * 128
#define NP     10000     // 2*8*25*25 patches
#define MT     79        // ceil(10000/128)
#define NT     15        // 1920/128

// ---------------- scratch (device globals, no allocs allowed) -----------
__device__ __nv_bfloat16 g_Hb[NP * HID];        // relu(emb@W1+b1), bf16
__device__ __nv_bfloat16 g_W2Tb[NPAD * HID];    // W2^T padded, bf16 [n][k]
__device__ float    g_center[NP];
__device__ float    g_valid[NP];
__device__ int      g_noff[NPAD];               // per-n gt window offset, -1 pad
__device__ uint32_t g_wpk[2 * DHW];             // packed (min|max<<16) 2x2 window
__device__ double   g_acc[3];                   // num, sum(m*p*p), sum(m*t)

// ======================= helpers ==========================
__device__ __forceinline__ uint32_t smem_u32(const void* p) {
    uint32_t a;
    asm("{ .reg .u64 t; cvta.to.shared.u64 t, %1; cvt.u32.u64 %0, t; }"
        : "=r"(a) : "l"(p));
    return a;
}
__device__ __forceinline__ float sigmoid_mufu(float z) {
    float u = -1.4426950408889634f * z;
    float ez; asm("ex2.approx.f32 %0, %1;" : "=f"(ez) : "f"(u));
    float d = 1.0f + ez;
    float r; asm("rcp.approx.f32 %0, %1;" : "=f"(r) : "f"(d));
    return r;
}

// ============================ prep ======================================
__global__ void k_prep(const float* __restrict__ W2) {
    int idx = blockIdx.x * 256 + threadIdx.x;          // 0 .. 491519
    if (idx < 3) g_acc[idx] = 0.0;
    if (idx < NPAD) {
        int n = idx;
        if (n < NPATCH) {
            int dp = n / 361, rr = n - dp * 361;
            int ii = rr / 19, jw = rr - ii * 19;
            g_noff[n] = dp * HW_ + 2 * ii * WW + 2 * jw;
        } else g_noff[n] = -1;
    }
    int k = idx / NPAD;
    int n = idx - k * NPAD;
    float v = (n < NPATCH) ? W2[k * NPATCH + n] : 0.f;
    g_W2Tb[n * HID + k] = __float2bfloat16(v);
}

// ======== packed window min/max field over gt (2x2, stride-1 grid) ======
__global__ void k_window(const float* __restrict__ target) {
    int idx = blockIdx.x * 256 + threadIdx.x;          // 2*DHW
    int b = idx / DHW; int r = idx - b * DHW;
    int d = r / HW_;   int hw = r - d * HW_;
    int h = hw >> 8;   int w = hw & 255;
    const float* g = target + (long)b * 4 * DHW + d * HW_ + hw;
    float g0 = g[0];
    float g1 = (w < 255) ? g[1] : g0;
    float g2 = (h < 255) ? g[WW] : g0;
    float g3 = (h < 255 && w < 255) ? g[WW + 1] : g0;
    int mn = (int)fminf(fminf(g0, g1), fminf(g2, g3));
    int mx = (int)fmaxf(fmaxf(g0, g1), fmaxf(g2, g3));
    g_wpk[idx] = (uint32_t)mn | ((uint32_t)mx << 16);
}

// ====================== emb gather + MLP1 (bf16 out) ====================
#define PPB 50
__global__ __launch_bounds__(256)
void k_mlp1(const float* __restrict__ target, const float* __restrict__ pred,
            const float* __restrict__ W1, const float* __restrict__ b1) {
    __shared__ float W1s[CEc * HID];
    __shared__ float embs[PPB * CEc];
    int tid = threadIdx.x;
    int pbase = blockIdx.x * PPB;

    for (int i = tid; i < CEc * HID; i += 256) W1s[i] = W1[i];

    for (int i = tid; i < PPB * CEc; i += 256) {
        int c = i / PPB, p = i - c * PPB;
        int n = pbase + p;
        int b = n / 5000;  int r = n - b * 5000;
        int pd = r / 625;  int r2 = r - pd * 625;
        int ph = r2 / 25;  int pw = r2 - ph * 25;
        int sp = ((2 + pd) * HH + (21 + 9 * ph)) * WW + (21 + 9 * pw);
        embs[p * CEc + c] = pred[(b * CEc + c) * DHW + sp];
    }
    if (tid < PPB) {
        int n = pbase + tid;
        int b = n / 5000;  int r = n - b * 5000;
        int pd = r / 625;  int r2 = r - pd * 625;
        int ph = r2 / 25;  int pw = r2 - ph * 25;
        int sp = ((2 + pd) * HH + (21 + 9 * ph)) * WW + (21 + 9 * pw);
        const float* tg = target + b * 4 * DHW;
        float c0 = tg[sp];
        float a1 = tg[1 * DHW + sp];
        float a2 = tg[2 * DHW + sp];
        float a3 = tg[3 * DHW + sp];
        g_center[n] = c0;
        g_valid[n] = (c0 != 0.f && a1 == 1.f && a2 == 1.f && a3 == 1.f) ? 1.f : 0.f;
    }
    __syncthreads();

    float bb = b1[tid];
    for (int p = 0; p < PPB; p++) {
        float acc = bb;
        const float* e = &embs[p * CEc];
#pragma unroll
        for (int c = 0; c < CEc; c++) acc = fmaf(e[c], W1s[c * HID + tid], acc);
        g_Hb[(pbase + p) * HID + tid] = __float2bfloat16(fmaxf(acc, 0.f));
    }
}

// ============ mma.sync bf16 GEMM (h @ W2) + fused epilogue ==============
// 4-stage cp.async pipeline (dynamic smem, 64KB), ONE barrier per k-iter.
// A/B tiles 128x32 bf16 = 8KB each; row stride 64B; chunk swizzle.
#define STG 4
#define STAGE_BYTES 8192
#define SMEM_DYN (STG * 2 * STAGE_BYTES)       // 65536

__global__ __launch_bounds__(256, 2)
void k_gemm(const uint32_t* __restrict__ gwp, const float* __restrict__ b2) {
    extern __shared__ __align__(128) char sm[];
    char* As = sm;                              // STG * 8KB
    char* Bs = sm + STG * STAGE_BYTES;          // STG * 8KB

    int tid = threadIdx.x;
    int wid = tid >> 5, lane = tid & 31;
    int n0 = blockIdx.x * 128;
    int m0 = blockIdx.y * 128;

    float c[4][4][4];
#pragma unroll
    for (int mi = 0; mi < 4; mi++)
#pragma unroll
        for (int ni = 0; ni < 4; ni++)
#pragma unroll
            for (int k = 0; k < 4; k++) c[mi][ni][k] = 0.f;

    int wm = (wid >> 2) * 64;     // warp m-base within tile
    int wn = (wid & 3) * 32;      // warp n-base within tile
    int jj = lane >> 3, rr = lane & 7;

    // ---- precompute ldmatrix smem addresses (stage 0) ----
    uint32_t aA[2][4], bA[2][2];
    uint32_t abase = smem_u32(As);
    uint32_t bbase = smem_u32(Bs);
#pragma unroll
    for (int s = 0; s < 2; s++) {
#pragma unroll
        for (int mi = 0; mi < 4; mi++) {
            int mrow = wm + mi * 16 + (jj & 1) * 8 + rr;
            int ch = s * 2 + (jj >> 1);
            aA[s][mi] = abase + mrow * 64 + ((ch ^ ((mrow >> 1) & 3)) * 16);
        }
#pragma unroll
        for (int nb = 0; nb < 2; nb++) {
            int nrow = wn + nb * 16 + (jj >> 1) * 8 + rr;
            int ch = s * 2 + (jj & 1);
            bA[s][nb] = bbase + nrow * 64 + ((ch ^ ((nrow >> 1) & 3)) * 16);
        }
    }

    // ---- precompute per-thread staging addresses (2 chunks per matrix) ----
    uint32_t stDst[2];
    const char* stA[2];
    const char* stB[2];
    int stSz[2];
#pragma unroll
    for (int l = 0; l < 2; l++) {
        int i = l * 256 + tid;
        int r = i >> 2;
        int cch = i & 3;
        stDst[l] = (uint32_t)(r * 64 + ((cch ^ ((r >> 1) & 3)) * 16));
        bool ok = (m0 + r < NP);
        stA[l] = ok ? (const char*)&g_Hb[(m0 + r) * HID + cch * 8]
                    : (const char*)&g_Hb[0];
        stSz[l] = ok ? 16 : 0;
        stB[l] = (const char*)&g_W2Tb[(n0 + r) * HID + cch * 8];
    }

    auto stage = [&](int it, int buf) {
        int koff = it * 64;                    // 32 bf16 = 64 bytes
#pragma unroll
        for (int l = 0; l < 2; l++) {
            uint32_t da = abase + buf * STAGE_BYTES + stDst[l];
            uint32_t db = bbase + buf * STAGE_BYTES + stDst[l];
            asm volatile("cp.async.cg.shared.global [%0], [%1], 16, %2;\n"
                         :: "r"(da), "l"(stA[l] + koff), "r"(stSz[l]));
            asm volatile("cp.async.cg.shared.global [%0], [%1], 16;\n"
                         :: "r"(db), "l"(stB[l] + koff));
        }
        asm volatile("cp.async.commit_group;\n" ::: "memory");
    };

    stage(0, 0);
    stage(1, 1);
    stage(2, 2);
    for (int it = 0; it < 8; it++) {
        // ensure stage "it" is resident
        if (it < 6)
            asm volatile("cp.async.wait_group 2;\n" ::: "memory");
        else if (it == 6)
            asm volatile("cp.async.wait_group 1;\n" ::: "memory");
        else
            asm volatile("cp.async.wait_group 0;\n" ::: "memory");
        __syncthreads();   // single barrier: also fences reuse of buf (it+3)&3
        if (it + 3 < 8) stage(it + 3, (it + 3) & 3);

        uint32_t boff = (uint32_t)((it & 3) * STAGE_BYTES);
#pragma unroll
        for (int s = 0; s < 2; s++) {
            uint32_t a[4][4], b[2][4];
#pragma unroll
            for (int mi = 0; mi < 4; mi++)
                asm volatile(
                    "ldmatrix.sync.aligned.m8n8.x4.shared.b16 {%0,%1,%2,%3}, [%4];"
                    : "=r"(a[mi][0]), "=r"(a[mi][1]), "=r"(a[mi][2]), "=r"(a[mi][3])
                    : "r"(aA[s][mi] + boff));
#pragma unroll
            for (int nb = 0; nb < 2; nb++)
                asm volatile(
                    "ldmatrix.sync.aligned.m8n8.x4.shared.b16 {%0,%1,%2,%3}, [%4];"
                    : "=r"(b[nb][0]), "=r"(b[nb][1]), "=r"(b[nb][2]), "=r"(b[nb][3])
                    : "r"(bA[s][nb] + boff));
#pragma unroll
            for (int mi = 0; mi < 4; mi++)
#pragma unroll
                for (int ni = 0; ni < 4; ni++) {
                    uint32_t bb0 = b[ni >> 1][(ni & 1) * 2 + 0];
                    uint32_t bb1 = b[ni >> 1][(ni & 1) * 2 + 1];
                    asm volatile(
                        "mma.sync.aligned.m16n8k16.row.col.f32.bf16.bf16.f32 "
                        "{%0,%1,%2,%3},{%4,%5,%6,%7},{%8,%9},{%0,%1,%2,%3};"
                        : "+f"(c[mi][ni][0]), "+f"(c[mi][ni][1]),
                          "+f"(c[mi][ni][2]), "+f"(c[mi][ni][3])
                        : "r"(a[mi][0]), "r"(a[mi][1]), "r"(a[mi][2]), "r"(a[mi][3]),
                          "r"(bb0), "r"(bb1));
                }
        }
    }

    // ---- per-thread n-metadata (registers, not smem) ----
    int   off8[8];
    float b28[8];
#pragma unroll
    for (int ni = 0; ni < 4; ni++)
#pragma unroll
        for (int q = 0; q < 2; q++) {
            int n = n0 + wn + ni * 8 + (lane & 3) * 2 + q;
            int o = __ldg(&g_noff[n]);
            off8[ni * 2 + q] = o;
            b28[ni * 2 + q] = (o >= 0) ? __ldg(&b2[n]) : 0.f;
        }

    // ---- fused epilogue: sigmoid + masks from packed window field ----
    float s_num = 0.f, s_dp = 0.f, s_dt = 0.f;
#pragma unroll
    for (int mi = 0; mi < 4; mi++)
#pragma unroll
        for (int h = 0; h < 2; h++) {
            int mloc = wm + mi * 16 + (lane >> 2) + h * 8;
            int m = m0 + mloc;
            if (m >= NP) continue;
            float vfl = g_valid[m];
            if (vfl == 0.f) continue;
            uint32_t cenpk = (uint32_t)(int)g_center[m] * 0x10001u;
            int b_ = m / 5000;  int r_ = m - b_ * 5000;
            int pd = r_ / 625;  int r2 = r_ - pd * 625;
            int ph = r2 / 25;   int pw = r2 - ph * 25;
            long gb = (long)(b_ * DD + pd) * HW_
                    + (2 + 9 * ph) * WW + (2 + 9 * pw);
#pragma unroll
            for (int ni = 0; ni < 4; ni++)
#pragma unroll
                for (int q = 0; q < 2; q++) {
                    int off = off8[ni * 2 + q];
                    if (off < 0) continue;
                    uint32_t w = __ldg(&gwp[gb + off]);
                    float tgt = (w != cenpk) ? 1.f : 0.f;
                    float msk = ((w & 0xFFFFu) == 0u) ? 0.f : vfl;
                    float z = c[mi][ni][h * 2 + q] + b28[ni * 2 + q];
                    float p = sigmoid_mufu(z);
                    float pm = p * msk;
                    s_num = fmaf(pm, tgt, s_num);
                    s_dp  = fmaf(pm, p,  s_dp);
                    s_dt  = fmaf(msk, tgt, s_dt);
                }
        }

    // ---- reduce (scratch reuses A tile) + atomics ----
#pragma unroll
    for (int o = 16; o; o >>= 1) {
        s_num += __shfl_xor_sync(0xffffffffu, s_num, o);
        s_dp  += __shfl_xor_sync(0xffffffffu, s_dp,  o);
        s_dt  += __shfl_xor_sync(0xffffffffu, s_dt,  o);
    }
    float* red = (float*)As;
    __syncthreads();
    if (lane == 0) {
        red[wid * 3 + 0] = s_num;
        red[wid * 3 + 1] = s_dp;
        red[wid * 3 + 2] = s_dt;
    }
    __syncthreads();
    if (tid == 0) {
        float a0 = 0, a1 = 0, a2 = 0;
#pragma unroll
        for (int w = 0; w < 8; w++) {
            a0 += red[w * 3 + 0]; a1 += red[w * 3 + 1]; a2 += red[w * 3 + 2];
        }
        atomicAdd(&g_acc[0], (double)a0);
        atomicAdd(&g_acc[1], (double)a1);
        atomicAdd(&g_acc[2], (double)a2);
    }
}

// ============================ final =====================================
__global__ void k_final(float* out) {
    double num = g_acc[0];
    double den = g_acc[1] + g_acc[2];
    if (den < 1e-6) den = 1e-6;
    out[0] = (float)(-2.0 * num / den);
}

// ============================ launch ====================================
extern "C" void kernel_launch(void* const* d_in, const int* in_sizes, int n_in,
                              void* d_out, int out_size) {
    const float* target = (const float*)d_in[0];
    const float* pred   = (const float*)d_in[1];
    const float* W1     = (const float*)d_in[2];
    const float* b1     = (const float*)d_in[3];
    const float* W2     = (const float*)d_in[4];
    const float* b2     = (const float*)d_in[5];

    uint32_t* gwp;
    cudaGetSymbolAddress((void**)&gwp, g_wpk);

    static int init_done = 0;
    if (!init_done) {
        cudaFuncSetAttribute(k_gemm, cudaFuncAttributeMaxDynamicSharedMemorySize,
                             SMEM_DYN);
        init_done = 1;
    }

    k_prep<<<(HID * NPAD) / 256, 256>>>(W2);
    k_window<<<(2 * DHW) / 256, 256>>>(target);
    k_mlp1<<<NP / PPB, 256>>>(target, pred, W1, b1);
    k_gemm<<<dim3(NT, MT), 256, SMEM_DYN>>>(gwp, b2);
    k_final<<<1, 1>>>((float*)d_out);
}

// round 12
// speedup vs baseline: 3.1970x; 1.1298x over previous
#include <cuda_runtime.h>
#include <cuda_bf16.h>
#include <cstdint>

// ---------------- problem constants ----------------
#define DD   12
#define HH   256
#define WW   256
#define HW_  (HH*WW)
#define DHW  (DD*HH*WW)
#define CEc  32
#define HID  256
#define NPATCH 1805      // 5*19*19
#define NPAD   1920      // 15 * 128
#define NP     10000     // 2*8*25*25 patches
#define BM   64
#define MT   157         // ceil(10000/64)
#define NT   15          // 1920/128

// ---------------- scratch (device globals, no allocs allowed) -----------
__device__ __nv_bfloat16 g_Hb[NP * HID];        // relu(emb@W1+b1), bf16
__device__ __nv_bfloat16 g_W2Tb[NPAD * HID];    // W2^T padded, bf16 [n][k]
__device__ float    g_center[NP];
__device__ float    g_valid[NP];
__device__ int      g_noff[NPAD];               // per-n gt window offset, -1 pad
__device__ uint32_t g_wpk[2 * DHW];             // packed (min|max<<16) 2x2 window
__device__ double   g_acc[3];                   // num, sum(m*p*p), sum(m*t)

// ======================= helpers ==========================
__device__ __forceinline__ uint32_t smem_u32(const void* p) {
    uint32_t a;
    asm("{ .reg .u64 t; cvta.to.shared.u64 t, %1; cvt.u32.u64 %0, t; }"
        : "=r"(a) : "l"(p));
    return a;
}
__device__ __forceinline__ float sigmoid_mufu(float z) {
    float u = -1.4426950408889634f * z;
    float ez; asm("ex2.approx.f32 %0, %1;" : "=f"(ez) : "f"(u));
    float d = 1.0f + ez;
    float r; asm("rcp.approx.f32 %0, %1;" : "=f"(r) : "f"(d));
    return r;
}

// ============================ prep ======================================
__global__ void k_prep(const float* __restrict__ W2) {
    int idx = blockIdx.x * 256 + threadIdx.x;          // 0 .. 491519
    if (idx < 3) g_acc[idx] = 0.0;
    if (idx < NPAD) {
        int n = idx;
        if (n < NPATCH) {
            int dp = n / 361, rr = n - dp * 361;
            int ii = rr / 19, jw = rr - ii * 19;
            g_noff[n] = dp * HW_ + 2 * ii * WW + 2 * jw;
        } else g_noff[n] = -1;
    }
    int k = idx / NPAD;
    int n = idx - k * NPAD;
    float v = (n < NPATCH) ? W2[k * NPATCH + n] : 0.f;
    g_W2Tb[n * HID + k] = __float2bfloat16(v);
}

// ======== packed window min/max field over gt (2x2, stride-1 grid) ======
__global__ void k_window(const float* __restrict__ target) {
    int idx = blockIdx.x * 256 + threadIdx.x;          // 2*DHW
    int b = idx / DHW; int r = idx - b * DHW;
    int d = r / HW_;   int hw = r - d * HW_;
    int h = hw >> 8;   int w = hw & 255;
    const float* g = target + (long)b * 4 * DHW + d * HW_ + hw;
    float g0 = g[0];
    float g1 = (w < 255) ? g[1] : g0;
    float g2 = (h < 255) ? g[WW] : g0;
    float g3 = (h < 255 && w < 255) ? g[WW + 1] : g0;
    int mn = (int)fminf(fminf(g0, g1), fminf(g2, g3));
    int mx = (int)fmaxf(fmaxf(g0, g1), fmaxf(g2, g3));
    g_wpk[idx] = (uint32_t)mn | ((uint32_t)mx << 16);
}

// ====================== emb gather + MLP1 (bf16 out) ====================
#define PPB 50
__global__ __launch_bounds__(256)
void k_mlp1(const float* __restrict__ target, const float* __restrict__ pred,
            const float* __restrict__ W1, const float* __restrict__ b1) {
    __shared__ float W1s[CEc * HID];
    __shared__ float embs[PPB * CEc];
    int tid = threadIdx.x;
    int pbase = blockIdx.x * PPB;

    for (int i = tid; i < CEc * HID; i += 256) W1s[i] = W1[i];

    for (int i = tid; i < PPB * CEc; i += 256) {
        int c = i / PPB, p = i - c * PPB;
        int n = pbase + p;
        int b = n / 5000;  int r = n - b * 5000;
        int pd = r / 625;  int r2 = r - pd * 625;
        int ph = r2 / 25;  int pw = r2 - ph * 25;
        int sp = ((2 + pd) * HH + (21 + 9 * ph)) * WW + (21 + 9 * pw);
        embs[p * CEc + c] = pred[(b * CEc + c) * DHW + sp];
    }
    if (tid < PPB) {
        int n = pbase + tid;
        int b = n / 5000;  int r = n - b * 5000;
        int pd = r / 625;  int r2 = r - pd * 625;
        int ph = r2 / 25;  int pw = r2 - ph * 25;
        int sp = ((2 + pd) * HH + (21 + 9 * ph)) * WW + (21 + 9 * pw);
        const float* tg = target + b * 4 * DHW;
        float c0 = tg[sp];
        float a1 = tg[1 * DHW + sp];
        float a2 = tg[2 * DHW + sp];
        float a3 = tg[3 * DHW + sp];
        g_center[n] = c0;
        g_valid[n] = (c0 != 0.f && a1 == 1.f && a2 == 1.f && a3 == 1.f) ? 1.f : 0.f;
    }
    __syncthreads();

    float bb = b1[tid];
    for (int p = 0; p < PPB; p++) {
        float acc = bb;
        const float* e = &embs[p * CEc];
#pragma unroll
        for (int c = 0; c < CEc; c++) acc = fmaf(e[c], W1s[c * HID + tid], acc);
        g_Hb[(pbase + p) * HID + tid] = __float2bfloat16(fmaxf(acc, 0.f));
    }
}

// ============ mma.sync bf16 GEMM (h @ W2) + fused epilogue ==============
// CTA tile 64x128, 8 warps (warp tile 32x32), 4-stage cp.async, BK=32.
// Stage: A 64x32 bf16 = 4KB, B 128x32 bf16 = 8KB.  Occ target: 3 CTAs/SM.
#define STG 4
#define A_BYTES 4096
#define B_BYTES 8192
#define STAGE_BYTES (A_BYTES + B_BYTES)        // 12288
#define SMEM_DYN (STG * STAGE_BYTES)           // 49152

__global__ __launch_bounds__(256, 3)
void k_gemm(const uint32_t* __restrict__ gwp, const float* __restrict__ b2) {
    extern __shared__ __align__(128) char sm[];

    int tid = threadIdx.x;
    int wid = tid >> 5, lane = tid & 31;
    int n0 = blockIdx.x * 128;
    int m0 = blockIdx.y * BM;

    float c[2][4][4];
#pragma unroll
    for (int mi = 0; mi < 2; mi++)
#pragma unroll
        for (int ni = 0; ni < 4; ni++)
#pragma unroll
            for (int k = 0; k < 4; k++) c[mi][ni][k] = 0.f;

    int wm = (wid >> 2) * 32;     // warp m-base within tile (0/32)
    int wn = (wid & 3) * 32;      // warp n-base within tile
    int jj = lane >> 3, rr = lane & 7;

    uint32_t sbase = smem_u32(sm);

    // ---- precompute ldmatrix smem addresses (stage 0) ----
    // A at stage offset 0, B at stage offset A_BYTES.
    uint32_t aA[2][2], bA[2][2];
#pragma unroll
    for (int s = 0; s < 2; s++) {
#pragma unroll
        for (int mi = 0; mi < 2; mi++) {
            int mrow = wm + mi * 16 + (jj & 1) * 8 + rr;
            int ch = s * 2 + (jj >> 1);
            aA[s][mi] = sbase + mrow * 64 + ((ch ^ ((mrow >> 1) & 3)) * 16);
        }
#pragma unroll
        for (int nb = 0; nb < 2; nb++) {
            int nrow = wn + nb * 16 + (jj >> 1) * 8 + rr;
            int ch = s * 2 + (jj & 1);
            bA[s][nb] = sbase + A_BYTES + nrow * 64
                      + ((ch ^ ((nrow >> 1) & 3)) * 16);
        }
    }

    // ---- staging: 768 16B-chunks/stage, 3 per thread (1 A + 2 B) ----
    // A chunk: thread t covers row = t>>2, chunk = t&3 (256 = 64 rows x 4)
    // B chunks: i = 256*l + t (l=1,2): row = (i-256)>>2, chunk = (i-256)&3
    uint32_t stDstA;
    const char* stSrcA;
    int stSzA;
    uint32_t stDstB[2];
    const char* stSrcB[2];
    {
        int r = tid >> 2, cch = tid & 3;
        stDstA = (uint32_t)(r * 64 + ((cch ^ ((r >> 1) & 3)) * 16));
        bool ok = (m0 + r < NP);
        stSrcA = ok ? (const char*)&g_Hb[(m0 + r) * HID + cch * 8]
                    : (const char*)&g_Hb[0];
        stSzA = ok ? 16 : 0;
#pragma unroll
        for (int l = 0; l < 2; l++) {
            int i = l * 256 + tid;
            int br = i >> 2, bc = i & 3;
            stDstB[l] = (uint32_t)(A_BYTES + br * 64 + ((bc ^ ((br >> 1) & 3)) * 16));
            stSrcB[l] = (const char*)&g_W2Tb[(n0 + br) * HID + bc * 8];
        }
    }

    auto stage = [&](int it, int buf) {
        int koff = it * 64;                    // 32 bf16 = 64 bytes
        uint32_t sb = sbase + buf * STAGE_BYTES;
        asm volatile("cp.async.cg.shared.global [%0], [%1], 16, %2;\n"
                     :: "r"(sb + stDstA), "l"(stSrcA + koff), "r"(stSzA));
#pragma unroll
        for (int l = 0; l < 2; l++)
            asm volatile("cp.async.cg.shared.global [%0], [%1], 16;\n"
                         :: "r"(sb + stDstB[l]), "l"(stSrcB[l] + koff));
        asm volatile("cp.async.commit_group;\n" ::: "memory");
    };

    stage(0, 0);
    stage(1, 1);
    stage(2, 2);
    for (int it = 0; it < 8; it++) {
        if (it < 6)
            asm volatile("cp.async.wait_group 2;\n" ::: "memory");
        else if (it == 6)
            asm volatile("cp.async.wait_group 1;\n" ::: "memory");
        else
            asm volatile("cp.async.wait_group 0;\n" ::: "memory");
        __syncthreads();
        if (it + 3 < 8) stage(it + 3, (it + 3) & 3);

        uint32_t boff = (uint32_t)((it & 3) * STAGE_BYTES);
#pragma unroll
        for (int s = 0; s < 2; s++) {
            uint32_t a[2][4], b[2][4];
#pragma unroll
            for (int mi = 0; mi < 2; mi++)
                asm volatile(
                    "ldmatrix.sync.aligned.m8n8.x4.shared.b16 {%0,%1,%2,%3}, [%4];"
                    : "=r"(a[mi][0]), "=r"(a[mi][1]), "=r"(a[mi][2]), "=r"(a[mi][3])
                    : "r"(aA[s][mi] + boff));
#pragma unroll
            for (int nb = 0; nb < 2; nb++)
                asm volatile(
                    "ldmatrix.sync.aligned.m8n8.x4.shared.b16 {%0,%1,%2,%3}, [%4];"
                    : "=r"(b[nb][0]), "=r"(b[nb][1]), "=r"(b[nb][2]), "=r"(b[nb][3])
                    : "r"(bA[s][nb] + boff));
#pragma unroll
            for (int mi = 0; mi < 2; mi++)
#pragma unroll
                for (int ni = 0; ni < 4; ni++) {
                    uint32_t bb0 = b[ni >> 1][(ni & 1) * 2 + 0];
                    uint32_t bb1 = b[ni >> 1][(ni & 1) * 2 + 1];
                    asm volatile(
                        "mma.sync.aligned.m16n8k16.row.col.f32.bf16.bf16.f32 "
                        "{%0,%1,%2,%3},{%4,%5,%6,%7},{%8,%9},{%0,%1,%2,%3};"
                        : "+f"(c[mi][ni][0]), "+f"(c[mi][ni][1]),
                          "+f"(c[mi][ni][2]), "+f"(c[mi][ni][3])
                        : "r"(a[mi][0]), "r"(a[mi][1]), "r"(a[mi][2]), "r"(a[mi][3]),
                          "r"(bb0), "r"(bb1));
                }
        }
    }

    // ---- per-thread n-metadata (registers) ----
    int   off8[8];
    float b28[8];
#pragma unroll
    for (int ni = 0; ni < 4; ni++)
#pragma unroll
        for (int q = 0; q < 2; q++) {
            int n = n0 + wn + ni * 8 + (lane & 3) * 2 + q;
            int o = __ldg(&g_noff[n]);
            off8[ni * 2 + q] = o;
            b28[ni * 2 + q] = (o >= 0) ? __ldg(&b2[n]) : 0.f;
        }

    // ---- fused epilogue: sigmoid + masks from packed window field ----
    float s_num = 0.f, s_dp = 0.f, s_dt = 0.f;
#pragma unroll
    for (int mi = 0; mi < 2; mi++)
#pragma unroll
        for (int h = 0; h < 2; h++) {
            int mloc = wm + mi * 16 + (lane >> 2) + h * 8;
            int m = m0 + mloc;
            if (m >= NP) continue;
            float vfl = g_valid[m];
            if (vfl == 0.f) continue;
            uint32_t cenpk = (uint32_t)(int)g_center[m] * 0x10001u;
            int b_ = m / 5000;  int r_ = m - b_ * 5000;
            int pd = r_ / 625;  int r2 = r_ - pd * 625;
            int ph = r2 / 25;   int pw = r2 - ph * 25;
            long gb = (long)(b_ * DD + pd) * HW_
                    + (2 + 9 * ph) * WW + (2 + 9 * pw);
#pragma unroll
            for (int ni = 0; ni < 4; ni++)
#pragma unroll
                for (int q = 0; q < 2; q++) {
                    int off = off8[ni * 2 + q];
                    if (off < 0) continue;
                    uint32_t w = __ldg(&gwp[gb + off]);
                    float tgt = (w != cenpk) ? 1.f : 0.f;
                    float msk = ((w & 0xFFFFu) == 0u) ? 0.f : vfl;
                    float z = c[mi][ni][h * 2 + q] + b28[ni * 2 + q];
                    float p = sigmoid_mufu(z);
                    float pm = p * msk;
                    s_num = fmaf(pm, tgt, s_num);
                    s_dp  = fmaf(pm, p,  s_dp);
                    s_dt  = fmaf(msk, tgt, s_dt);
                }
        }

    // ---- reduce (scratch reuses tile smem) + atomics ----
#pragma unroll
    for (int o = 16; o; o >>= 1) {
        s_num += __shfl_xor_sync(0xffffffffu, s_num, o);
        s_dp  += __shfl_xor_sync(0xffffffffu, s_dp,  o);
        s_dt  += __shfl_xor_sync(0xffffffffu, s_dt,  o);
    }
    float* red = (float*)sm;
    __syncthreads();
    if (lane == 0) {
        red[wid * 3 + 0] = s_num;
        red[wid * 3 + 1] = s_dp;
        red[wid * 3 + 2] = s_dt;
    }
    __syncthreads();
    if (tid == 0) {
        float a0 = 0, a1 = 0, a2 = 0;
#pragma unroll
        for (int w = 0; w < 8; w++) {
            a0 += red[w * 3 + 0]; a1 += red[w * 3 + 1]; a2 += red[w * 3 + 2];
        }
        atomicAdd(&g_acc[0], (double)a0);
        atomicAdd(&g_acc[1], (double)a1);
        atomicAdd(&g_acc[2], (double)a2);
    }
}

// ============================ final =====================================
__global__ void k_final(float* out) {
    double num = g_acc[0];
    double den = g_acc[1] + g_acc[2];
    if (den < 1e-6) den = 1e-6;
    out[0] = (float)(-2.0 * num / den);
}

// ============================ launch ====================================
extern "C" void kernel_launch(void* const* d_in, const int* in_sizes, int n_in,
                              void* d_out, int out_size) {
    const float* target = (const float*)d_in[0];
    const float* pred   = (const float*)d_in[1];
    const float* W1     = (const float*)d_in[2];
    const float* b1     = (const float*)d_in[3];
    const float* W2     = (const float*)d_in[4];
    const float* b2     = (const float*)d_in[5];

    uint32_t* gwp;
    cudaGetSymbolAddress((void**)&gwp, g_wpk);

    static int init_done = 0;
    if (!init_done) {
        cudaFuncSetAttribute(k_gemm, cudaFuncAttributeMaxDynamicSharedMemorySize,
                             SMEM_DYN);
        init_done = 1;
    }

    k_prep<<<(HID * NPAD) / 256, 256>>>(W2);
    k_window<<<(2 * DHW) / 256, 256>>>(target);
    k_mlp1<<<NP / PPB, 256>>>(target, pred, W1, b1);
    k_gemm<<<dim3(NT, MT), 256, SMEM_DYN>>>(gwp, b2);
    k_final<<<1, 1>>>((float*)d_out);
}

// round 13
// speedup vs baseline: 3.3630x; 1.0519x over previous
#include <cuda_runtime.h>
#include <cuda_bf16.h>
#include <cstdint>

// ---------------- problem constants ----------------
#define DD   12
#define HH   256
#define WW   256
#define HW_  (HH*WW)
#define DHW  (DD*HH*WW)
#define CEc  32
#define HID  256
#define NPATCH 1805      // 5*19*19
#define NPAD   1920      // 15 * 128
#define NP     10000     // 2*8*25*25 patches
#define BM   64
#define MT   157         // ceil(10000/64)
#define NT   15          // 1920/128

// ---------------- scratch (device globals, no allocs allowed) -----------
__device__ __nv_bfloat16 g_Hb[NP * HID];        // relu(emb@W1+b1), bf16
__device__ __nv_bfloat16 g_W2Tb[NPAD * HID];    // W2^T padded, bf16 [n][k]
__device__ int2     g_mmeta[NP];                // {gb offset or -1, cenpk}
__device__ int      g_noff[NPAD];               // per-n gt window offset, -1 pad
__device__ uint32_t g_wpk[2 * DHW];             // packed (min|max<<16) 2x2 window
__device__ double   g_acc[3];                   // num, sum(m*p*p), sum(m*t)

// ======================= helpers ==========================
__device__ __forceinline__ uint32_t smem_u32(const void* p) {
    uint32_t a;
    asm("{ .reg .u64 t; cvta.to.shared.u64 t, %1; cvt.u32.u64 %0, t; }"
        : "=r"(a) : "l"(p));
    return a;
}
__device__ __forceinline__ float sigmoid_mufu(float z) {
    float u = -1.4426950408889634f * z;
    float ez; asm("ex2.approx.f32 %0, %1;" : "=f"(ez) : "f"(u));
    float d = 1.0f + ez;
    float r; asm("rcp.approx.f32 %0, %1;" : "=f"(r) : "f"(d));
    return r;
}

// ============================ prep ======================================
__global__ void k_prep(const float* __restrict__ W2) {
    int idx = blockIdx.x * 256 + threadIdx.x;          // 0 .. 491519
    if (idx < 3) g_acc[idx] = 0.0;
    if (idx < NPAD) {
        int n = idx;
        if (n < NPATCH) {
            int dp = n / 361, rr = n - dp * 361;
            int ii = rr / 19, jw = rr - ii * 19;
            g_noff[n] = dp * HW_ + 2 * ii * WW + 2 * jw;
        } else g_noff[n] = -1;
    }
    int k = idx / NPAD;
    int n = idx - k * NPAD;
    float v = (n < NPATCH) ? W2[k * NPATCH + n] : 0.f;
    g_W2Tb[n * HID + k] = __float2bfloat16(v);
}

// ======== packed window min/max field over gt (2x2, stride-1 grid) ======
__global__ void k_window(const float* __restrict__ target) {
    int idx = blockIdx.x * 256 + threadIdx.x;          // 2*DHW
    int b = idx / DHW; int r = idx - b * DHW;
    int d = r / HW_;   int hw = r - d * HW_;
    int h = hw >> 8;   int w = hw & 255;
    const float* g = target + (long)b * 4 * DHW + d * HW_ + hw;
    float g0 = g[0];
    float g1 = (w < 255) ? g[1] : g0;
    float g2 = (h < 255) ? g[WW] : g0;
    float g3 = (h < 255 && w < 255) ? g[WW + 1] : g0;
    int mn = (int)fminf(fminf(g0, g1), fminf(g2, g3));
    int mx = (int)fmaxf(fmaxf(g0, g1), fmaxf(g2, g3));
    g_wpk[idx] = (uint32_t)mn | ((uint32_t)mx << 16);
}

// ====================== emb gather + MLP1 (bf16 out) ====================
#define PPB 50
__global__ __launch_bounds__(256)
void k_mlp1(const float* __restrict__ target, const float* __restrict__ pred,
            const float* __restrict__ W1, const float* __restrict__ b1) {
    __shared__ float W1s[CEc * HID];
    __shared__ float embs[PPB * CEc];
    int tid = threadIdx.x;
    int pbase = blockIdx.x * PPB;

    for (int i = tid; i < CEc * HID; i += 256) W1s[i] = W1[i];

    for (int i = tid; i < PPB * CEc; i += 256) {
        int c = i / PPB, p = i - c * PPB;
        int n = pbase + p;
        int b = n / 5000;  int r = n - b * 5000;
        int pd = r / 625;  int r2 = r - pd * 625;
        int ph = r2 / 25;  int pw = r2 - ph * 25;
        int sp = ((2 + pd) * HH + (21 + 9 * ph)) * WW + (21 + 9 * pw);
        embs[p * CEc + c] = pred[(b * CEc + c) * DHW + sp];
    }
    if (tid < PPB) {
        int n = pbase + tid;
        int b = n / 5000;  int r = n - b * 5000;
        int pd = r / 625;  int r2 = r - pd * 625;
        int ph = r2 / 25;  int pw = r2 - ph * 25;
        int sp = ((2 + pd) * HH + (21 + 9 * ph)) * WW + (21 + 9 * pw);
        const float* tg = target + b * 4 * DHW;
        float c0 = tg[sp];
        float a1 = tg[1 * DHW + sp];
        float a2 = tg[2 * DHW + sp];
        float a3 = tg[3 * DHW + sp];
        bool valid = (c0 != 0.f && a1 == 1.f && a2 == 1.f && a3 == 1.f);
        int gb = (b * DD + pd) * HW_ + (2 + 9 * ph) * WW + (2 + 9 * pw);
        int2 meta;
        meta.x = valid ? gb : -1;
        meta.y = (int)((uint32_t)(int)c0 * 0x10001u);
        g_mmeta[n] = meta;
    }
    __syncthreads();

    float bb = b1[tid];
    for (int p = 0; p < PPB; p++) {
        float acc = bb;
        const float* e = &embs[p * CEc];
#pragma unroll
        for (int c = 0; c < CEc; c++) acc = fmaf(e[c], W1s[c * HID + tid], acc);
        g_Hb[(pbase + p) * HID + tid] = __float2bfloat16(fmaxf(acc, 0.f));
    }
}

// ============ mma.sync bf16 GEMM (h @ W2) + fused epilogue ==============
// CTA tile 64x128, 8 warps (warp tile 32x32), 4-stage cp.async, BK=32.
// Stage: A 64x32 bf16 = 4KB, B 128x32 bf16 = 8KB.  Occ target: 4 CTAs/SM.
#define STG 4
#define A_BYTES 4096
#define B_BYTES 8192
#define STAGE_BYTES (A_BYTES + B_BYTES)        // 12288
#define META_OFF (STG * STAGE_BYTES)           // 49152
#define SMEM_DYN (META_OFF + 1024)             // 50176

__global__ __launch_bounds__(256, 4)
void k_gemm(const uint32_t* __restrict__ gwp, const float* __restrict__ b2) {
    extern __shared__ __align__(128) char sm[];
    int*   noffs = (int*)(sm + META_OFF);          // [128]
    float* b2s   = (float*)(sm + META_OFF + 512);  // [128]

    int tid = threadIdx.x;
    int wid = tid >> 5, lane = tid & 31;
    int n0 = blockIdx.x * 128;
    int m0 = blockIdx.y * BM;

    if (tid < 128) {
        int n = n0 + tid;
        noffs[tid] = g_noff[n];
        b2s[tid]   = (n < NPATCH) ? __ldg(&b2[n]) : 0.f;
    }

    float c[2][4][4];
#pragma unroll
    for (int mi = 0; mi < 2; mi++)
#pragma unroll
        for (int ni = 0; ni < 4; ni++)
#pragma unroll
            for (int k = 0; k < 4; k++) c[mi][ni][k] = 0.f;

    int wm = (wid >> 2) * 32;     // warp m-base within tile (0/32)
    int wn = (wid & 3) * 32;      // warp n-base within tile
    int jj = lane >> 3, rr = lane & 7;

    uint32_t sbase = smem_u32(sm);

    // ---- precompute ldmatrix smem addresses (stage 0) ----
    uint32_t aA[2][2], bA[2][2];
#pragma unroll
    for (int s = 0; s < 2; s++) {
#pragma unroll
        for (int mi = 0; mi < 2; mi++) {
            int mrow = wm + mi * 16 + (jj & 1) * 8 + rr;
            int ch = s * 2 + (jj >> 1);
            aA[s][mi] = sbase + mrow * 64 + ((ch ^ ((mrow >> 1) & 3)) * 16);
        }
#pragma unroll
        for (int nb = 0; nb < 2; nb++) {
            int nrow = wn + nb * 16 + (jj >> 1) * 8 + rr;
            int ch = s * 2 + (jj & 1);
            bA[s][nb] = sbase + A_BYTES + nrow * 64
                      + ((ch ^ ((nrow >> 1) & 3)) * 16);
        }
    }

    // ---- staging: 768 16B-chunks/stage, 3 per thread (1 A + 2 B) ----
    // B chunk l=1 is l=0 plus constant offsets (64 rows): gmem +32768B, smem +4096B.
    uint32_t stDstA, stDstB;
    const char* stSrcA;
    const char* stSrcB;
    int stSzA;
    {
        int r = tid >> 2, cch = tid & 3;
        uint32_t swz = (uint32_t)((cch ^ ((r >> 1) & 3)) * 16);
        stDstA = (uint32_t)(r * 64) + swz;
        stDstB = A_BYTES + stDstA;
        bool ok = (m0 + r < NP);
        stSrcA = ok ? (const char*)&g_Hb[(m0 + r) * HID + cch * 8]
                    : (const char*)&g_Hb[0];
        stSzA = ok ? 16 : 0;
        stSrcB = (const char*)&g_W2Tb[(n0 + r) * HID + cch * 8];
    }

    auto stage = [&](int it, int buf) {
        int koff = it * 64;                    // 32 bf16 = 64 bytes
        uint32_t sb = sbase + buf * STAGE_BYTES;
        asm volatile("cp.async.cg.shared.global [%0], [%1], 16, %2;\n"
                     :: "r"(sb + stDstA), "l"(stSrcA + koff), "r"(stSzA));
        asm volatile("cp.async.cg.shared.global [%0], [%1], 16;\n"
                     :: "r"(sb + stDstB), "l"(stSrcB + koff));
        asm volatile("cp.async.cg.shared.global [%0], [%1], 16;\n"
                     :: "r"(sb + stDstB + 4096), "l"(stSrcB + 32768 + koff));
        asm volatile("cp.async.commit_group;\n" ::: "memory");
    };

    stage(0, 0);
    stage(1, 1);
    stage(2, 2);
    for (int it = 0; it < 8; it++) {
        if (it < 6)
            asm volatile("cp.async.wait_group 2;\n" ::: "memory");
        else if (it == 6)
            asm volatile("cp.async.wait_group 1;\n" ::: "memory");
        else
            asm volatile("cp.async.wait_group 0;\n" ::: "memory");
        __syncthreads();
        if (it + 3 < 8) stage(it + 3, (it + 3) & 3);

        uint32_t boff = (uint32_t)((it & 3) * STAGE_BYTES);
#pragma unroll
        for (int s = 0; s < 2; s++) {
            uint32_t a[2][4], b[2][4];
#pragma unroll
            for (int mi = 0; mi < 2; mi++)
                asm volatile(
                    "ldmatrix.sync.aligned.m8n8.x4.shared.b16 {%0,%1,%2,%3}, [%4];"
                    : "=r"(a[mi][0]), "=r"(a[mi][1]), "=r"(a[mi][2]), "=r"(a[mi][3])
                    : "r"(aA[s][mi] + boff));
#pragma unroll
            for (int nb = 0; nb < 2; nb++)
                asm volatile(
                    "ldmatrix.sync.aligned.m8n8.x4.shared.b16 {%0,%1,%2,%3}, [%4];"
                    : "=r"(b[nb][0]), "=r"(b[nb][1]), "=r"(b[nb][2]), "=r"(b[nb][3])
                    : "r"(bA[s][nb] + boff));
#pragma unroll
            for (int mi = 0; mi < 2; mi++)
#pragma unroll
                for (int ni = 0; ni < 4; ni++) {
                    uint32_t bb0 = b[ni >> 1][(ni & 1) * 2 + 0];
                    uint32_t bb1 = b[ni >> 1][(ni & 1) * 2 + 1];
                    asm volatile(
                        "mma.sync.aligned.m16n8k16.row.col.f32.bf16.bf16.f32 "
                        "{%0,%1,%2,%3},{%4,%5,%6,%7},{%8,%9},{%0,%1,%2,%3};"
                        : "+f"(c[mi][ni][0]), "+f"(c[mi][ni][1]),
                          "+f"(c[mi][ni][2]), "+f"(c[mi][ni][3])
                        : "r"(a[mi][0]), "r"(a[mi][1]), "r"(a[mi][2]), "r"(a[mi][3]),
                          "r"(bb0), "r"(bb1));
                }
        }
    }

    // ---- fused epilogue: sigmoid + masks via precomputed metadata ----
    float s_num = 0.f, s_dp = 0.f, s_dt = 0.f;
#pragma unroll
    for (int mi = 0; mi < 2; mi++)
#pragma unroll
        for (int h = 0; h < 2; h++) {
            int mloc = wm + mi * 16 + (lane >> 2) + h * 8;
            int m = m0 + mloc;
            if (m >= NP) continue;
            int2 meta = __ldg(&g_mmeta[m]);
            if (meta.x < 0) continue;                 // invalid center
            uint32_t cenpk = (uint32_t)meta.y;
            const uint32_t* gw = gwp + meta.x;
#pragma unroll
            for (int ni = 0; ni < 4; ni++)
#pragma unroll
                for (int q = 0; q < 2; q++) {
                    int nloc = wn + ni * 8 + (lane & 3) * 2 + q;
                    int off = noffs[nloc];
                    if (off < 0) continue;            // padded column
                    uint32_t w = __ldg(&gw[off]);
                    float tgt = (w != cenpk) ? 1.f : 0.f;
                    float msk = ((w & 0xFFFFu) == 0u) ? 0.f : 1.f;
                    float z = c[mi][ni][h * 2 + q] + b2s[nloc];
                    float p = sigmoid_mufu(z);
                    float pm = p * msk;
                    s_num = fmaf(pm, tgt, s_num);
                    s_dp  = fmaf(pm, p,  s_dp);
                    s_dt  = fmaf(msk, tgt, s_dt);
                }
        }

    // ---- reduce (scratch reuses tile smem) + atomics ----
#pragma unroll
    for (int o = 16; o; o >>= 1) {
        s_num += __shfl_xor_sync(0xffffffffu, s_num, o);
        s_dp  += __shfl_xor_sync(0xffffffffu, s_dp,  o);
        s_dt  += __shfl_xor_sync(0xffffffffu, s_dt,  o);
    }
    float* red = (float*)sm;
    __syncthreads();
    if (lane == 0) {
        red[wid * 3 + 0] = s_num;
        red[wid * 3 + 1] = s_dp;
        red[wid * 3 + 2] = s_dt;
    }
    __syncthreads();
    if (tid == 0) {
        float a0 = 0, a1 = 0, a2 = 0;
#pragma unroll
        for (int w = 0; w < 8; w++) {
            a0 += red[w * 3 + 0]; a1 += red[w * 3 + 1]; a2 += red[w * 3 + 2];
        }
        atomicAdd(&g_acc[0], (double)a0);
        atomicAdd(&g_acc[1], (double)a1);
        atomicAdd(&g_acc[2], (double)a2);
    }
}

// ============================ final =====================================
__global__ void k_final(float* out) {
    double num = g_acc[0];
    double den = g_acc[1] + g_acc[2];
    if (den < 1e-6) den = 1e-6;
    out[0] = (float)(-2.0 * num / den);
}

// ============================ launch ====================================
extern "C" void kernel_launch(void* const* d_in, const int* in_sizes, int n_in,
                              void* d_out, int out_size) {
    const float* target = (const float*)d_in[0];
    const float* pred   = (const float*)d_in[1];
    const float* W1     = (const float*)d_in[2];
    const float* b1     = (const float*)d_in[3];
    const float* W2     = (const float*)d_in[4];
    const float* b2     = (const float*)d_in[5];

    uint32_t* gwp;
    cudaGetSymbolAddress((void**)&gwp, g_wpk);

    static int init_done = 0;
    if (!init_done) {
        cudaFuncSetAttribute(k_gemm, cudaFuncAttributeMaxDynamicSharedMemorySize,
                             SMEM_DYN);
        init_done = 1;
    }

    k_prep<<<(HID * NPAD) / 256, 256>>>(W2);
    k_window<<<(2 * DHW) / 256, 256>>>(target);
    k_mlp1<<<NP / PPB, 256>>>(target, pred, W1, b1);
    k_gemm<<<dim3(NT, MT), 256, SMEM_DYN>>>(gwp, b2);
    k_final<<<1, 1>>>((float*)d_out);
}

// round 14
// speedup vs baseline: 3.7391x; 1.1119x over previous
#include <cuda_runtime.h>
#include <cuda_bf16.h>
#include <cstdint>

// ---------------- problem constants ----------------
#define DD   12
#define HH   256
#define WW   256
#define HW_  (HH*WW)
#define DHW  (DD*HH*WW)
#define CEc  32
#define HID  256
#define NPATCH 1805      // 5*19*19
#define NPAD   1920      // 15 * 128
#define NP     10000     // 2*8*25*25 patches
#define BM   64
#define MT   157         // ceil(10000/64)
#define NT   15          // 1920/128
#define NCTA (MT * NT)   // 2355

// ---------------- scratch (device globals, no allocs allowed) -----------
__device__ __nv_bfloat16 g_Hb[NP * HID];        // relu(emb@W1+b1), bf16
__device__ __nv_bfloat16 g_W2Tb[NPAD * HID];    // W2^T padded, bf16 [n][k]
__device__ int2     g_mmeta[NP];                // {gb offset or -1, cenpk}
__device__ int      g_noff[NPAD];               // per-n gt window offset, -1 pad
__device__ uint32_t g_wpk[2 * DHW];             // packed (min|max<<16) 2x2 window
__device__ double   g_acc[3];                   // num, sum(m*p*p), sum(m*t)
__device__ unsigned g_done;                     // completion counter

// ======================= helpers ==========================
__device__ __forceinline__ uint32_t smem_u32(const void* p) {
    uint32_t a;
    asm("{ .reg .u64 t; cvta.to.shared.u64 t, %1; cvt.u32.u64 %0, t; }"
        : "=r"(a) : "l"(p));
    return a;
}
__device__ __forceinline__ float sigmoid_mufu(float z) {
    float u = -1.4426950408889634f * z;
    float ez; asm("ex2.approx.f32 %0, %1;" : "=f"(ez) : "f"(u));
    float d = 1.0f + ez;
    float r; asm("rcp.approx.f32 %0, %1;" : "=f"(r) : "f"(d));
    return r;
}

// ============== fused prep (W2^T, LUTs, counters) + window field ========
// grid: 6144 blocks x 256 = 1,572,864 threads (= 2*DHW)
__global__ void k_prep_window(const float* __restrict__ W2,
                              const float* __restrict__ target) {
    int idx = blockIdx.x * 256 + threadIdx.x;

    // --- packed 2x2 window min/max over gt ---
    {
        int b = idx / DHW; int r = idx - b * DHW;
        int d = r / HW_;   int hw = r - d * HW_;
        int h = hw >> 8;   int w = hw & 255;
        const float* g = target + (long)b * 4 * DHW + d * HW_ + hw;
        float g0 = g[0];
        float g1 = (w < 255) ? g[1] : g0;
        float g2 = (h < 255) ? g[WW] : g0;
        float g3 = (h < 255 && w < 255) ? g[WW + 1] : g0;
        int mn = (int)fminf(fminf(g0, g1), fminf(g2, g3));
        int mx = (int)fmaxf(fmaxf(g0, g1), fmaxf(g2, g3));
        g_wpk[idx] = (uint32_t)mn | ((uint32_t)mx << 16);
    }

    // --- prep part (first 491,520 threads) ---
    if (idx < 3) g_acc[idx] = 0.0;
    if (idx == 3) g_done = 0u;
    if (idx < NPAD) {
        int n = idx;
        if (n < NPATCH) {
            int dp = n / 361, rr = n - dp * 361;
            int ii = rr / 19, jw = rr - ii * 19;
            g_noff[n] = dp * HW_ + 2 * ii * WW + 2 * jw;
        } else g_noff[n] = -1;
    }
    if (idx < HID * NPAD) {
        int k = idx / NPAD;
        int n = idx - k * NPAD;
        float v = (n < NPATCH) ? W2[k * NPATCH + n] : 0.f;
        g_W2Tb[n * HID + k] = __float2bfloat16(v);
    }
}

// ====================== emb gather + MLP1 (bf16 out) ====================
#define PPB 25   // 400 blocks
__global__ __launch_bounds__(256)
void k_mlp1(const float* __restrict__ target, const float* __restrict__ pred,
            const float* __restrict__ W1, const float* __restrict__ b1) {
    __shared__ float W1s[CEc * HID];
    __shared__ float embs[PPB * CEc];
    int tid = threadIdx.x;
    int pbase = blockIdx.x * PPB;

    for (int i = tid; i < CEc * HID; i += 256) W1s[i] = W1[i];

    for (int i = tid; i < PPB * CEc; i += 256) {
        int c = i / PPB, p = i - c * PPB;
        int n = pbase + p;
        int b = n / 5000;  int r = n - b * 5000;
        int pd = r / 625;  int r2 = r - pd * 625;
        int ph = r2 / 25;  int pw = r2 - ph * 25;
        int sp = ((2 + pd) * HH + (21 + 9 * ph)) * WW + (21 + 9 * pw);
        embs[p * CEc + c] = pred[(b * CEc + c) * DHW + sp];
    }
    if (tid < PPB) {
        int n = pbase + tid;
        int b = n / 5000;  int r = n - b * 5000;
        int pd = r / 625;  int r2 = r - pd * 625;
        int ph = r2 / 25;  int pw = r2 - ph * 25;
        int sp = ((2 + pd) * HH + (21 + 9 * ph)) * WW + (21 + 9 * pw);
        const float* tg = target + b * 4 * DHW;
        float c0 = tg[sp];
        float a1 = tg[1 * DHW + sp];
        float a2 = tg[2 * DHW + sp];
        float a3 = tg[3 * DHW + sp];
        bool valid = (c0 != 0.f && a1 == 1.f && a2 == 1.f && a3 == 1.f);
        int gb = (b * DD + pd) * HW_ + (2 + 9 * ph) * WW + (2 + 9 * pw);
        int2 meta;
        meta.x = valid ? gb : -1;
        meta.y = (int)((uint32_t)(int)c0 * 0x10001u);
        g_mmeta[n] = meta;
    }
    __syncthreads();

    float bb = b1[tid];
    for (int p = 0; p < PPB; p++) {
        float acc = bb;
        const float* e = &embs[p * CEc];
#pragma unroll
        for (int c = 0; c < CEc; c++) acc = fmaf(e[c], W1s[c * HID + tid], acc);
        g_Hb[(pbase + p) * HID + tid] = __float2bfloat16(fmaxf(acc, 0.f));
    }
}

// ============ mma.sync bf16 GEMM (h @ W2) + fused epilogue + final ======
// CTA tile 64x128, 8 warps (warp tile 32x32), 4-stage cp.async, BK=32.
#define STG 4
#define A_BYTES 4096
#define B_BYTES 8192
#define STAGE_BYTES (A_BYTES + B_BYTES)        // 12288
#define META_OFF (STG * STAGE_BYTES)           // 49152
#define SMEM_DYN (META_OFF + 1024)             // 50176

__global__ __launch_bounds__(256, 4)
void k_gemm(const uint32_t* __restrict__ gwp, const float* __restrict__ b2,
            float* __restrict__ out) {
    extern __shared__ __align__(128) char sm[];
    int*   noffs = (int*)(sm + META_OFF);          // [128]
    float* b2s   = (float*)(sm + META_OFF + 512);  // [128]

    int tid = threadIdx.x;
    int wid = tid >> 5, lane = tid & 31;
    int n0 = blockIdx.x * 128;
    int m0 = blockIdx.y * BM;

    if (tid < 128) {
        int n = n0 + tid;
        noffs[tid] = g_noff[n];
        b2s[tid]   = (n < NPATCH) ? __ldg(&b2[n]) : 0.f;
    }

    float c[2][4][4];
#pragma unroll
    for (int mi = 0; mi < 2; mi++)
#pragma unroll
        for (int ni = 0; ni < 4; ni++)
#pragma unroll
            for (int k = 0; k < 4; k++) c[mi][ni][k] = 0.f;

    int wm = (wid >> 2) * 32;     // warp m-base within tile (0/32)
    int wn = (wid & 3) * 32;      // warp n-base within tile
    int jj = lane >> 3, rr = lane & 7;

    uint32_t sbase = smem_u32(sm);

    // ---- precompute ldmatrix smem addresses (stage 0) ----
    uint32_t aA[2][2], bA[2][2];
#pragma unroll
    for (int s = 0; s < 2; s++) {
#pragma unroll
        for (int mi = 0; mi < 2; mi++) {
            int mrow = wm + mi * 16 + (jj & 1) * 8 + rr;
            int ch = s * 2 + (jj >> 1);
            aA[s][mi] = sbase + mrow * 64 + ((ch ^ ((mrow >> 1) & 3)) * 16);
        }
#pragma unroll
        for (int nb = 0; nb < 2; nb++) {
            int nrow = wn + nb * 16 + (jj >> 1) * 8 + rr;
            int ch = s * 2 + (jj & 1);
            bA[s][nb] = sbase + A_BYTES + nrow * 64
                      + ((ch ^ ((nrow >> 1) & 3)) * 16);
        }
    }

    // ---- staging: 768 16B-chunks/stage, 3 per thread (1 A + 2 B) ----
    uint32_t stDstA, stDstB;
    const char* stSrcA;
    const char* stSrcB;
    int stSzA;
    {
        int r = tid >> 2, cch = tid & 3;
        uint32_t swz = (uint32_t)((cch ^ ((r >> 1) & 3)) * 16);
        stDstA = (uint32_t)(r * 64) + swz;
        stDstB = A_BYTES + stDstA;
        bool ok = (m0 + r < NP);
        stSrcA = ok ? (const char*)&g_Hb[(m0 + r) * HID + cch * 8]
                    : (const char*)&g_Hb[0];
        stSzA = ok ? 16 : 0;
        stSrcB = (const char*)&g_W2Tb[(n0 + r) * HID + cch * 8];
    }

    auto stage = [&](int it, int buf) {
        int koff = it * 64;                    // 32 bf16 = 64 bytes
        uint32_t sb = sbase + buf * STAGE_BYTES;
        asm volatile("cp.async.cg.shared.global [%0], [%1], 16, %2;\n"
                     :: "r"(sb + stDstA), "l"(stSrcA + koff), "r"(stSzA));
        asm volatile("cp.async.cg.shared.global [%0], [%1], 16;\n"
                     :: "r"(sb + stDstB), "l"(stSrcB + koff));
        asm volatile("cp.async.cg.shared.global [%0], [%1], 16;\n"
                     :: "r"(sb + stDstB + 4096), "l"(stSrcB + 32768 + koff));
        asm volatile("cp.async.commit_group;\n" ::: "memory");
    };

    stage(0, 0);
    stage(1, 1);
    stage(2, 2);
    for (int it = 0; it < 8; it++) {
        if (it < 6)
            asm volatile("cp.async.wait_group 2;\n" ::: "memory");
        else if (it == 6)
            asm volatile("cp.async.wait_group 1;\n" ::: "memory");
        else
            asm volatile("cp.async.wait_group 0;\n" ::: "memory");
        __syncthreads();
        if (it + 3 < 8) stage(it + 3, (it + 3) & 3);

        uint32_t boff = (uint32_t)((it & 3) * STAGE_BYTES);
#pragma unroll
        for (int s = 0; s < 2; s++) {
            uint32_t a[2][4], b[2][4];
#pragma unroll
            for (int mi = 0; mi < 2; mi++)
                asm volatile(
                    "ldmatrix.sync.aligned.m8n8.x4.shared.b16 {%0,%1,%2,%3}, [%4];"
                    : "=r"(a[mi][0]), "=r"(a[mi][1]), "=r"(a[mi][2]), "=r"(a[mi][3])
                    : "r"(aA[s][mi] + boff));
#pragma unroll
            for (int nb = 0; nb < 2; nb++)
                asm volatile(
                    "ldmatrix.sync.aligned.m8n8.x4.shared.b16 {%0,%1,%2,%3}, [%4];"
                    : "=r"(b[nb][0]), "=r"(b[nb][1]), "=r"(b[nb][2]), "=r"(b[nb][3])
                    : "r"(bA[s][nb] + boff));
#pragma unroll
            for (int mi = 0; mi < 2; mi++)
#pragma unroll
                for (int ni = 0; ni < 4; ni++) {
                    uint32_t bb0 = b[ni >> 1][(ni & 1) * 2 + 0];
                    uint32_t bb1 = b[ni >> 1][(ni & 1) * 2 + 1];
                    asm volatile(
                        "mma.sync.aligned.m16n8k16.row.col.f32.bf16.bf16.f32 "
                        "{%0,%1,%2,%3},{%4,%5,%6,%7},{%8,%9},{%0,%1,%2,%3};"
                        : "+f"(c[mi][ni][0]), "+f"(c[mi][ni][1]),
                          "+f"(c[mi][ni][2]), "+f"(c[mi][ni][3])
                        : "r"(a[mi][0]), "r"(a[mi][1]), "r"(a[mi][2]), "r"(a[mi][3]),
                          "r"(bb0), "r"(bb1));
                }
        }
    }

    // ---- fused epilogue: sigmoid + masks via precomputed metadata ----
    float s_num = 0.f, s_dp = 0.f, s_dt = 0.f;
#pragma unroll
    for (int mi = 0; mi < 2; mi++)
#pragma unroll
        for (int h = 0; h < 2; h++) {
            int mloc = wm + mi * 16 + (lane >> 2) + h * 8;
            int m = m0 + mloc;
            if (m >= NP) continue;
            int2 meta = __ldg(&g_mmeta[m]);
            if (meta.x < 0) continue;                 // invalid center
            uint32_t cenpk = (uint32_t)meta.y;
            const uint32_t* gw = gwp + meta.x;
#pragma unroll
            for (int ni = 0; ni < 4; ni++)
#pragma unroll
                for (int q = 0; q < 2; q++) {
                    int nloc = wn + ni * 8 + (lane & 3) * 2 + q;
                    int off = noffs[nloc];
                    if (off < 0) continue;            // padded column
                    uint32_t w = __ldg(&gw[off]);
                    float tgt = (w != cenpk) ? 1.f : 0.f;
                    float msk = ((w & 0xFFFFu) == 0u) ? 0.f : 1.f;
                    float z = c[mi][ni][h * 2 + q] + b2s[nloc];
                    float p = sigmoid_mufu(z);
                    float pm = p * msk;
                    s_num = fmaf(pm, tgt, s_num);
                    s_dp  = fmaf(pm, p,  s_dp);
                    s_dt  = fmaf(msk, tgt, s_dt);
                }
        }

    // ---- reduce (scratch reuses tile smem) + atomics + fused final ----
#pragma unroll
    for (int o = 16; o; o >>= 1) {
        s_num += __shfl_xor_sync(0xffffffffu, s_num, o);
        s_dp  += __shfl_xor_sync(0xffffffffu, s_dp,  o);
        s_dt  += __shfl_xor_sync(0xffffffffu, s_dt,  o);
    }
    float* red = (float*)sm;
    __syncthreads();
    if (lane == 0) {
        red[wid * 3 + 0] = s_num;
        red[wid * 3 + 1] = s_dp;
        red[wid * 3 + 2] = s_dt;
    }
    __syncthreads();
    if (tid == 0) {
        float a0 = 0, a1 = 0, a2 = 0;
#pragma unroll
        for (int w = 0; w < 8; w++) {
            a0 += red[w * 3 + 0]; a1 += red[w * 3 + 1]; a2 += red[w * 3 + 2];
        }
        atomicAdd(&g_acc[0], (double)a0);
        atomicAdd(&g_acc[1], (double)a1);
        atomicAdd(&g_acc[2], (double)a2);
        __threadfence();
        unsigned ticket = atomicAdd(&g_done, 1u);
        if (ticket == NCTA - 1) {                 // last CTA: finalize
            double num = g_acc[0];
            double den = g_acc[1] + g_acc[2];
            if (den < 1e-6) den = 1e-6;
            out[0] = (float)(-2.0 * num / den);
        }
    }
}

// ============================ launch ====================================
extern "C" void kernel_launch(void* const* d_in, const int* in_sizes, int n_in,
                              void* d_out, int out_size) {
    const float* target = (const float*)d_in[0];
    const float* pred   = (const float*)d_in[1];
    const float* W1     = (const float*)d_in[2];
    const float* b1     = (const float*)d_in[3];
    const float* W2     = (const float*)d_in[4];
    const float* b2     = (const float*)d_in[5];

    uint32_t* gwp;
    cudaGetSymbolAddress((void**)&gwp, g_wpk);

    static int init_done = 0;
    if (!init_done) {
        cudaFuncSetAttribute(k_gemm, cudaFuncAttributeMaxDynamicSharedMemorySize,
                             SMEM_DYN);
        init_done = 1;
    }

    k_prep_window<<<(2 * DHW) / 256, 256>>>(W2, target);
    k_mlp1<<<NP / PPB, 256>>>(target, pred, W1, b1);
    k_gemm<<<dim3(NT, MT), 256, SMEM_DYN>>>(gwp, b2, (float*)d_out);
}

// round 15
// speedup vs baseline: 3.7885x; 1.0132x over previous
#include <cuda_runtime.h>
#include <cuda_bf16.h>
#include <cstdint>

// ---------------- problem constants ----------------
#define DD   12
#define HH   256
#define WW   256
#define HW_  (HH*WW)
#define DHW  (DD*HH*WW)
#define CEc  32
#define HID  256
#define NPATCH 1805      // 5*19*19
#define NPAD   1920      // 15 * 128
#define NP     10000     // 2*8*25*25 patches
#define BM   64
#define MT   157         // ceil(10000/64)
#define NT   15          // 1920/128
#define NCTA (MT * NT)   // 2355

// ---------------- scratch (device globals, no allocs allowed) -----------
__device__ __nv_bfloat16 g_Hb[NP * HID];        // relu(emb@W1+b1), bf16
__device__ __nv_bfloat16 g_W2Tb[NPAD * HID];    // W2^T padded, bf16 [n][k]
__device__ int2     g_mmeta[NP];                // {gb offset or -1, cenpk}
__device__ int      g_noff[NPAD];               // per-n gt window offset, -1 pad
__device__ uint32_t g_wpk[2 * DHW];             // packed (min|max<<16) 2x2 window
__device__ double   g_acc[3];                   // num, sum(m*p*p), sum(m*t)
__device__ unsigned g_done;                     // completion counter

// ======================= helpers ==========================
__device__ __forceinline__ uint32_t smem_u32(const void* p) {
    uint32_t a;
    asm("{ .reg .u64 t; cvta.to.shared.u64 t, %1; cvt.u32.u64 %0, t; }"
        : "=r"(a) : "l"(p));
    return a;
}
__device__ __forceinline__ float sigmoid_mufu(float z) {
    float u = -1.4426950408889634f * z;
    float ez; asm("ex2.approx.f32 %0, %1;" : "=f"(ez) : "f"(u));
    float d = 1.0f + ez;
    float r; asm("rcp.approx.f32 %0, %1;" : "=f"(r) : "f"(d));
    return r;
}
__device__ __forceinline__ uint32_t pack_mnmx(float a, float b, float c, float d) {
    int mn = (int)fminf(fminf(a, b), fminf(c, d));
    int mx = (int)fmaxf(fmaxf(a, b), fmaxf(c, d));
    return (uint32_t)mn | ((uint32_t)mx << 16);
}

// ============== fused prep (W2^T, LUTs, counters) + window field ========
// grid: 1920 blocks x 256 = 491,520 threads.
// Window part: first 393,216 threads, 4 outputs each (float4 vectorized).
// W2^T part: all 491,520 threads, 1 element each.
#define PW_THREADS (2 * DHW / 4)   // 393216
__global__ void k_prep_window(const float* __restrict__ W2,
                              const float* __restrict__ target) {
    int idx = blockIdx.x * 256 + threadIdx.x;

    // --- packed 2x2 window min/max over gt, 4 outputs per thread ---
    if (idx < PW_THREADS) {
        int i4 = idx * 4;
        int b = i4 / DHW; int r = i4 - b * DHW;
        int d = r / HW_;  int hw = r - d * HW_;
        int h = hw >> 8;  int w = hw & 255;          // w multiple of 4
        const float* g = target + (long)b * 4 * DHW + d * HW_ + hw;
        float4 v0 = *(const float4*)g;
        float  e0 = (w < 252) ? g[4] : v0.w;         // clamp at row end
        float4 v1; float e1;
        if (h < 255) {
            v1 = *(const float4*)(g + WW);
            e1 = (w < 252) ? g[WW + 4] : v1.w;
        } else { v1 = v0; e1 = e0; }
        uint4 out;
        out.x = pack_mnmx(v0.x, v0.y, v1.x, v1.y);
        out.y = pack_mnmx(v0.y, v0.z, v1.y, v1.z);
        out.z = pack_mnmx(v0.z, v0.w, v1.z, v1.w);
        out.w = pack_mnmx(v0.w, e0,   v1.w, e1);
        *(uint4*)&g_wpk[i4] = out;
    }

    // --- prep part ---
    if (idx < 3) g_acc[idx] = 0.0;
    if (idx == 3) g_done = 0u;
    if (idx < NPAD) {
        int n = idx;
        if (n < NPATCH) {
            int dp = n / 361, rr = n - dp * 361;
            int ii = rr / 19, jw = rr - ii * 19;
            g_noff[n] = dp * HW_ + 2 * ii * WW + 2 * jw;
        } else g_noff[n] = -1;
    }
    {
        int k = idx / NPAD;
        int n = idx - k * NPAD;
        float v = (n < NPATCH) ? W2[k * NPATCH + n] : 0.f;
        g_W2Tb[n * HID + k] = __float2bfloat16(v);
    }
}

// ====================== emb gather + MLP1 (bf16 out) ====================
#define PPB 25   // 400 blocks
__global__ __launch_bounds__(256)
void k_mlp1(const float* __restrict__ target, const float* __restrict__ pred,
            const float* __restrict__ W1, const float* __restrict__ b1) {
    __shared__ float W1s[CEc * HID];
    __shared__ float embs[PPB * CEc];
    int tid = threadIdx.x;
    int pbase = blockIdx.x * PPB;

    for (int i = tid; i < CEc * HID; i += 256) W1s[i] = W1[i];

    for (int i = tid; i < PPB * CEc; i += 256) {
        int c = i / PPB, p = i - c * PPB;
        int n = pbase + p;
        int b = n / 5000;  int r = n - b * 5000;
        int pd = r / 625;  int r2 = r - pd * 625;
        int ph = r2 / 25;  int pw = r2 - ph * 25;
        int sp = ((2 + pd) * HH + (21 + 9 * ph)) * WW + (21 + 9 * pw);
        embs[p * CEc + c] = pred[(b * CEc + c) * DHW + sp];
    }
    if (tid < PPB) {
        int n = pbase + tid;
        int b = n / 5000;  int r = n - b * 5000;
        int pd = r / 625;  int r2 = r - pd * 625;
        int ph = r2 / 25;  int pw = r2 - ph * 25;
        int sp = ((2 + pd) * HH + (21 + 9 * ph)) * WW + (21 + 9 * pw);
        const float* tg = target + b * 4 * DHW;
        float c0 = tg[sp];
        float a1 = tg[1 * DHW + sp];
        float a2 = tg[2 * DHW + sp];
        float a3 = tg[3 * DHW + sp];
        bool valid = (c0 != 0.f && a1 == 1.f && a2 == 1.f && a3 == 1.f);
        int gb = (b * DD + pd) * HW_ + (2 + 9 * ph) * WW + (2 + 9 * pw);
        int2 meta;
        meta.x = valid ? gb : -1;
        meta.y = (int)((uint32_t)(int)c0 * 0x10001u);
        g_mmeta[n] = meta;
    }
    __syncthreads();

    float bb = b1[tid];
    for (int p = 0; p < PPB; p++) {
        float acc = bb;
        const float* e = &embs[p * CEc];
#pragma unroll
        for (int c = 0; c < CEc; c++) acc = fmaf(e[c], W1s[c * HID + tid], acc);
        g_Hb[(pbase + p) * HID + tid] = __float2bfloat16(fmaxf(acc, 0.f));
    }
}

// ============ mma.sync bf16 GEMM (h @ W2) + fused epilogue + final ======
// CTA tile 64x128, 8 warps (warp tile 32x32), 4-stage cp.async, BK=32.
#define STG 4
#define A_BYTES 4096
#define B_BYTES 8192
#define STAGE_BYTES (A_BYTES + B_BYTES)        // 12288
#define META_OFF (STG * STAGE_BYTES)           // 49152
#define SMEM_DYN (META_OFF + 1024)             // 50176

__global__ __launch_bounds__(256, 4)
void k_gemm(const uint32_t* __restrict__ gwp, const float* __restrict__ b2,
            float* __restrict__ out) {
    extern __shared__ __align__(128) char sm[];
    int*   noffs = (int*)(sm + META_OFF);          // [128]
    float* b2s   = (float*)(sm + META_OFF + 512);  // [128]

    int tid = threadIdx.x;
    int wid = tid >> 5, lane = tid & 31;
    int n0 = blockIdx.x * 128;
    int m0 = blockIdx.y * BM;

    if (tid < 128) {
        int n = n0 + tid;
        noffs[tid] = g_noff[n];
        b2s[tid]   = (n < NPATCH) ? __ldg(&b2[n]) : 0.f;
    }

    float c[2][4][4];
#pragma unroll
    for (int mi = 0; mi < 2; mi++)
#pragma unroll
        for (int ni = 0; ni < 4; ni++)
#pragma unroll
            for (int k = 0; k < 4; k++) c[mi][ni][k] = 0.f;

    int wm = (wid >> 2) * 32;     // warp m-base within tile (0/32)
    int wn = (wid & 3) * 32;      // warp n-base within tile
    int jj = lane >> 3, rr = lane & 7;

    uint32_t sbase = smem_u32(sm);

    // ---- precompute ldmatrix smem addresses (stage 0) ----
    uint32_t aA[2][2], bA[2][2];
#pragma unroll
    for (int s = 0; s < 2; s++) {
#pragma unroll
        for (int mi = 0; mi < 2; mi++) {
            int mrow = wm + mi * 16 + (jj & 1) * 8 + rr;
            int ch = s * 2 + (jj >> 1);
            aA[s][mi] = sbase + mrow * 64 + ((ch ^ ((mrow >> 1) & 3)) * 16);
        }
#pragma unroll
        for (int nb = 0; nb < 2; nb++) {
            int nrow = wn + nb * 16 + (jj >> 1) * 8 + rr;
            int ch = s * 2 + (jj & 1);
            bA[s][nb] = sbase + A_BYTES + nrow * 64
                      + ((ch ^ ((nrow >> 1) & 3)) * 16);
        }
    }

    // ---- staging: 768 16B-chunks/stage, 3 per thread (1 A + 2 B) ----
    uint32_t stDstA, stDstB;
    const char* stSrcA;
    const char* stSrcB;
    int stSzA;
    {
        int r = tid >> 2, cch = tid & 3;
        uint32_t swz = (uint32_t)((cch ^ ((r >> 1) & 3)) * 16);
        stDstA = (uint32_t)(r * 64) + swz;
        stDstB = A_BYTES + stDstA;
        bool ok = (m0 + r < NP);
        stSrcA = ok ? (const char*)&g_Hb[(m0 + r) * HID + cch * 8]
                    : (const char*)&g_Hb[0];
        stSzA = ok ? 16 : 0;
        stSrcB = (const char*)&g_W2Tb[(n0 + r) * HID + cch * 8];
    }

    auto stage = [&](int it, int buf) {
        int koff = it * 64;                    // 32 bf16 = 64 bytes
        uint32_t sb = sbase + buf * STAGE_BYTES;
        asm volatile("cp.async.cg.shared.global [%0], [%1], 16, %2;\n"
                     :: "r"(sb + stDstA), "l"(stSrcA + koff), "r"(stSzA));
        asm volatile("cp.async.cg.shared.global [%0], [%1], 16;\n"
                     :: "r"(sb + stDstB), "l"(stSrcB + koff));
        asm volatile("cp.async.cg.shared.global [%0], [%1], 16;\n"
                     :: "r"(sb + stDstB + 4096), "l"(stSrcB + 32768 + koff));
        asm volatile("cp.async.commit_group;\n" ::: "memory");
    };

    stage(0, 0);
    stage(1, 1);
    stage(2, 2);
    for (int it = 0; it < 8; it++) {
        if (it < 6)
            asm volatile("cp.async.wait_group 2;\n" ::: "memory");
        else if (it == 6)
            asm volatile("cp.async.wait_group 1;\n" ::: "memory");
        else
            asm volatile("cp.async.wait_group 0;\n" ::: "memory");
        __syncthreads();
        if (it + 3 < 8) stage(it + 3, (it + 3) & 3);

        uint32_t boff = (uint32_t)((it & 3) * STAGE_BYTES);
#pragma unroll
        for (int s = 0; s < 2; s++) {
            uint32_t a[2][4], b[2][4];
#pragma unroll
            for (int mi = 0; mi < 2; mi++)
                asm volatile(
                    "ldmatrix.sync.aligned.m8n8.x4.shared.b16 {%0,%1,%2,%3}, [%4];"
                    : "=r"(a[mi][0]), "=r"(a[mi][1]), "=r"(a[mi][2]), "=r"(a[mi][3])
                    : "r"(aA[s][mi] + boff));
#pragma unroll
            for (int nb = 0; nb < 2; nb++)
                asm volatile(
                    "ldmatrix.sync.aligned.m8n8.x4.shared.b16 {%0,%1,%2,%3}, [%4];"
                    : "=r"(b[nb][0]), "=r"(b[nb][1]), "=r"(b[nb][2]), "=r"(b[nb][3])
                    : "r"(bA[s][nb] + boff));
#pragma unroll
            for (int mi = 0; mi < 2; mi++)
#pragma unroll
                for (int ni = 0; ni < 4; ni++) {
                    uint32_t bb0 = b[ni >> 1][(ni & 1) * 2 + 0];
                    uint32_t bb1 = b[ni >> 1][(ni & 1) * 2 + 1];
                    asm volatile(
                        "mma.sync.aligned.m16n8k16.row.col.f32.bf16.bf16.f32 "
                        "{%0,%1,%2,%3},{%4,%5,%6,%7},{%8,%9},{%0,%1,%2,%3};"
                        : "+f"(c[mi][ni][0]), "+f"(c[mi][ni][1]),
                          "+f"(c[mi][ni][2]), "+f"(c[mi][ni][3])
                        : "r"(a[mi][0]), "r"(a[mi][1]), "r"(a[mi][2]), "r"(a[mi][3]),
                          "r"(bb0), "r"(bb1));
                }
        }
    }

    // ---- fused epilogue: sigmoid + masks via precomputed metadata ----
    float s_num = 0.f, s_dp = 0.f, s_dt = 0.f;
#pragma unroll
    for (int mi = 0; mi < 2; mi++)
#pragma unroll
        for (int h = 0; h < 2; h++) {
            int mloc = wm + mi * 16 + (lane >> 2) + h * 8;
            int m = m0 + mloc;
            if (m >= NP) continue;
            int2 meta = __ldg(&g_mmeta[m]);
            if (meta.x < 0) continue;                 // invalid center
            uint32_t cenpk = (uint32_t)meta.y;
            const uint32_t* gw = gwp + meta.x;
#pragma unroll
            for (int ni = 0; ni < 4; ni++)
#pragma unroll
                for (int q = 0; q < 2; q++) {
                    int nloc = wn + ni * 8 + (lane & 3) * 2 + q;
                    int off = noffs[nloc];
                    if (off < 0) continue;            // padded column
                    uint32_t w = __ldg(&gw[off]);
                    float tgt = (w != cenpk) ? 1.f : 0.f;
                    float msk = ((w & 0xFFFFu) == 0u) ? 0.f : 1.f;
                    float z = c[mi][ni][h * 2 + q] + b2s[nloc];
                    float p = sigmoid_mufu(z);
                    float pm = p * msk;
                    s_num = fmaf(pm, tgt, s_num);
                    s_dp  = fmaf(pm, p,  s_dp);
                    s_dt  = fmaf(msk, tgt, s_dt);
                }
        }

    // ---- reduce (scratch reuses tile smem) + atomics + fused final ----
#pragma unroll
    for (int o = 16; o; o >>= 1) {
        s_num += __shfl_xor_sync(0xffffffffu, s_num, o);
        s_dp  += __shfl_xor_sync(0xffffffffu, s_dp,  o);
        s_dt  += __shfl_xor_sync(0xffffffffu, s_dt,  o);
    }
    float* red = (float*)sm;
    __syncthreads();
    if (lane == 0) {
        red[wid * 3 + 0] = s_num;
        red[wid * 3 + 1] = s_dp;
        red[wid * 3 + 2] = s_dt;
    }
    __syncthreads();
    if (tid == 0) {
        float a0 = 0, a1 = 0, a2 = 0;
#pragma unroll
        for (int w = 0; w < 8; w++) {
            a0 += red[w * 3 + 0]; a1 += red[w * 3 + 1]; a2 += red[w * 3 + 2];
        }
        atomicAdd(&g_acc[0], (double)a0);
        atomicAdd(&g_acc[1], (double)a1);
        atomicAdd(&g_acc[2], (double)a2);
        __threadfence();
        unsigned ticket = atomicAdd(&g_done, 1u);
        if (ticket == NCTA - 1) {                 // last CTA: finalize
            double num = g_acc[0];
            double den = g_acc[1] + g_acc[2];
            if (den < 1e-6) den = 1e-6;
            out[0] = (float)(-2.0 * num / den);
        }
    }
}

// ============================ launch ====================================
extern "C" void kernel_launch(void* const* d_in, const int* in_sizes, int n_in,
                              void* d_out, int out_size) {
    const float* target = (const float*)d_in[0];
    const float* pred   = (const float*)d_in[1];
    const float* W1     = (const float*)d_in[2];
    const float* b1     = (const float*)d_in[3];
    const float* W2     = (const float*)d_in[4];
    const float* b2     = (const float*)d_in[5];

    uint32_t* gwp;
    cudaGetSymbolAddress((void**)&gwp, g_wpk);

    static int init_done = 0;
    if (!init_done) {
        cudaFuncSetAttribute(k_gemm, cudaFuncAttributeMaxDynamicSharedMemorySize,
                             SMEM_DYN);
        init_done = 1;
    }

    k_prep_window<<<(HID * NPAD) / 256, 256>>>(W2, target);
    k_mlp1<<<NP / PPB, 256>>>(target, pred, W1, b1);
    k_gemm<<<dim3(NT, MT), 256, SMEM_DYN>>>(gwp, b2, (float*)d_out);
}